// round 8
// baseline (speedup 1.0000x reference)
#include <cuda_runtime.h>

#define N_NODES 4096
#define IN_DIM  512
#define HD      512   // H * ATT_DIM
#define ATT_DIM 64

// Scratch (device globals: allocation-free per harness rules)
__device__ float g_q[N_NODES * HD];
__device__ float g_k[N_NODES * HD];
__device__ float g_v[N_NODES * HD];
__device__ float g_att[N_NODES * HD];

// ---------------------------------------------------------------------------
// tf32 helpers
// ---------------------------------------------------------------------------
__device__ __forceinline__ unsigned f2tf(float f) {
    unsigned u;
    asm("cvt.rna.tf32.f32 %0, %1;" : "=r"(u) : "f"(f));
    return u;
}

// split x into hi (tf32) + lo (tf32 of remainder); hi+lo ~ 22-bit mantissa
__device__ __forceinline__ void tf32_split(float x, unsigned& hi, unsigned& lo) {
    hi = f2tf(x);
    lo = f2tf(x - __uint_as_float(hi));
}

__device__ __forceinline__ void mma_tf32(float c[4],
                                         const unsigned a[4],
                                         unsigned b0, unsigned b1) {
    asm volatile(
        "mma.sync.aligned.m16n8k8.row.col.f32.tf32.tf32.f32 "
        "{%0,%1,%2,%3}, {%4,%5,%6,%7}, {%8,%9}, {%0,%1,%2,%3};"
        : "+f"(c[0]), "+f"(c[1]), "+f"(c[2]), "+f"(c[3])
        : "r"(a[0]), "r"(a[1]), "r"(a[2]), "r"(a[3]), "r"(b0), "r"(b1));
}

// p = exp(sigmoid(s) + 0.1*a)   [the -0.5 bias is constant: cancels in softmax]
// sigmoid: EX2 + RCP (2 MUFU). exp on t in (0,1.1): deg-5 Taylor about 0.55
// (coeffs e^0.55 / i!), rel err <~7e-5 (common-mode part cancels in softmax).
__device__ __forceinline__ float fast_p(float s, float a) {
    float e;
    asm("ex2.approx.f32 %0, %1;" : "=f"(e) : "f"(-1.442695041f * s));
    float r;
    asm("rcp.approx.f32 %0, %1;" : "=f"(r) : "f"(1.0f + e));
    float u = fmaf(0.1f, a, r - 0.55f);
    float p = fmaf(0.01444378f, u, 0.07221888f);
    p = fmaf(p, u, 0.28887550f);
    p = fmaf(p, u, 0.86662651f);
    p = fmaf(p, u, 1.73325302f);
    p = fmaf(p, u, 1.73325302f);
    return p;
}

// ---------------------------------------------------------------------------
// Projection GEMM via SPLIT-tf32 mma (fp32-grade accuracy):
//   C = (A[4096,512] @ W[512,512] + bias) * scale, outputs tf32-rounded.
// Each operand split hi/lo; acc += Ah*Bh + Ah*Bl + Al*Bh (lo*lo dropped,
// ~2^-22 relative — negligible). CTA 128x128, 8 warps (32m x 64n), BK=16.
// ---------------------------------------------------------------------------
__global__ __launch_bounds__(256) void proj_mma(const float* __restrict__ A,
                                                const float* __restrict__ W,
                                                const float* __restrict__ bias,
                                                float* __restrict__ C,
                                                float scale) {
    __shared__ float As[16 * 136];
    __shared__ float Bs[16 * 136];

    const int tid  = threadIdx.x;
    const int w    = tid >> 5;
    const int lane = tid & 31;
    const int g    = lane >> 2;
    const int t4   = lane & 3;
    const int m0   = (w >> 1) * 32;
    const int n0   = (w & 1) * 64;
    const int bm   = blockIdx.y * 128;
    const int bn   = blockIdx.x * 128;

    const int arow  = tid >> 1;
    const int ahalf = (tid & 1) * 8;
    const int aswz  = (ahalf & 8) << 1;      // 0 or 16
    const int brow  = tid >> 4;              // 0..15
    const int bcolg = (tid & 15) * 8;

    float acc[2][8][4];
#pragma unroll
    for (int mi = 0; mi < 2; mi++)
#pragma unroll
        for (int ni = 0; ni < 8; ni++)
#pragma unroll
            for (int r = 0; r < 4; r++) acc[mi][ni][r] = 0.f;

    for (int k0 = 0; k0 < IN_DIM; k0 += 16) {
        float4 av0 = *(const float4*)&A[(size_t)(bm + arow) * IN_DIM + k0 + ahalf];
        float4 av1 = *(const float4*)&A[(size_t)(bm + arow) * IN_DIM + k0 + ahalf + 4];
        float4 bv0 = *(const float4*)&W[(size_t)(k0 + brow) * HD + bn + bcolg];
        float4 bv1 = *(const float4*)&W[(size_t)(k0 + brow) * HD + bn + bcolg + 4];
        __syncthreads();
        {
            const int mi_ = arow ^ aswz;
            As[(ahalf + 0) * 136 + mi_] = av0.x;
            As[(ahalf + 1) * 136 + mi_] = av0.y;
            As[(ahalf + 2) * 136 + mi_] = av0.z;
            As[(ahalf + 3) * 136 + mi_] = av0.w;
            As[(ahalf + 4) * 136 + mi_] = av1.x;
            As[(ahalf + 5) * 136 + mi_] = av1.y;
            As[(ahalf + 6) * 136 + mi_] = av1.z;
            As[(ahalf + 7) * 136 + mi_] = av1.w;
            *(float4*)&Bs[brow * 136 + bcolg]     = bv0;
            *(float4*)&Bs[brow * 136 + bcolg + 4] = bv1;
        }
        __syncthreads();

#pragma unroll
        for (int s = 0; s < 2; s++) {
            const int swz = s << 4;
            unsigned ah[2][4], al[2][4];
#pragma unroll
            for (int mi = 0; mi < 2; mi++) {
                const int mrow = m0 + mi * 16 + g;
                tf32_split(As[(s * 8 + t4) * 136 + (mrow ^ swz)],        ah[mi][0], al[mi][0]);
                tf32_split(As[(s * 8 + t4) * 136 + ((mrow + 8) ^ swz)],  ah[mi][1], al[mi][1]);
                tf32_split(As[(s * 8 + t4 + 4) * 136 + (mrow ^ swz)],       ah[mi][2], al[mi][2]);
                tf32_split(As[(s * 8 + t4 + 4) * 136 + ((mrow + 8) ^ swz)], ah[mi][3], al[mi][3]);
            }
#pragma unroll
            for (int ni = 0; ni < 8; ni++) {
                unsigned bh0, bl0, bh1, bl1;
                tf32_split(Bs[(s * 8 + t4) * 136 + n0 + ni * 8 + g],     bh0, bl0);
                tf32_split(Bs[(s * 8 + t4 + 4) * 136 + n0 + ni * 8 + g], bh1, bl1);
#pragma unroll
                for (int mi = 0; mi < 2; mi++) {
                    mma_tf32(acc[mi][ni], ah[mi], bh0, bh1);  // hi*hi
                    mma_tf32(acc[mi][ni], ah[mi], bl0, bl1);  // hi*lo
                    mma_tf32(acc[mi][ni], al[mi], bh0, bh1);  // lo*hi
                }
            }
        }
    }

    // epilogue: (acc + bias) * scale, tf32-round (same as R5), store float2
#pragma unroll
    for (int mi = 0; mi < 2; mi++) {
        const int r0 = bm + m0 + mi * 16 + g;
#pragma unroll
        for (int ni = 0; ni < 8; ni++) {
            const int col = bn + n0 + ni * 8 + 2 * t4;
            const float b0 = bias[col], b1 = bias[col + 1];
            float2 o0, o1;
            o0.x = __uint_as_float(f2tf((acc[mi][ni][0] + b0) * scale));
            o0.y = __uint_as_float(f2tf((acc[mi][ni][1] + b1) * scale));
            o1.x = __uint_as_float(f2tf((acc[mi][ni][2] + b0) * scale));
            o1.y = __uint_as_float(f2tf((acc[mi][ni][3] + b1) * scale));
            *(float2*)&C[(size_t)r0 * HD + col]       = o0;
            *(float2*)&C[(size_t)(r0 + 8) * HD + col] = o1;
        }
    }
}

// ---------------------------------------------------------------------------
// Attention via mma.sync m16n8k8 tf32, n-outer restructure.
// CTA = 128 queries x 1 head, 4 warps x 32 rows (2 m-tiles).
// Per key-tile (8 keys): S-mma -> softmax (EX2+RCP+poly) -> C-frag->A-frag via
// shuffles -> PV-mma immediately. Only 8 score regs live; no P smem.
// ---------------------------------------------------------------------------
#define KP 72   // k_s/v_s pitch: 72 == 8 (mod 32) -> conflict-free B-frag reads

__global__ __launch_bounds__(128, 3) void attn_mma(const float* __restrict__ adj) {
    __shared__ float k_s[64 * KP];   // [d][j] transposed
    __shared__ float v_s[64 * KP];   // [j][e]

    const int tid  = threadIdx.x;
    const int w    = tid >> 5;
    const int lane = tid & 31;
    const int g    = lane >> 2;
    const int t4   = lane & 3;
    const int qb   = blockIdx.x;      // 0..31
    const int h    = blockIdx.y;      // 0..7
    const int hoff = h * ATT_DIM;
    const int qrow0 = qb * 128 + w * 32;

    const int base = lane & 28;             // g*4
    const int s1   = base + (t4 >> 1);      // shuffle src for cols t4
    const int s2   = s1 + 2;                // shuffle src for cols t4+4
    const bool odd = (t4 & 1);

    // q A-fragments resident in registers (g_q already tf32-rounded + scaled)
    unsigned qa[2][8][4];
#pragma unroll
    for (int mi = 0; mi < 2; mi++) {
        const float* r0 = &g_q[(size_t)(qrow0 + mi * 16 + g) * HD + hoff];
        const float* r1 = &g_q[(size_t)(qrow0 + mi * 16 + g + 8) * HD + hoff];
#pragma unroll
        for (int kc = 0; kc < 8; kc++) {
            qa[mi][kc][0] = __float_as_uint(r0[kc * 8 + t4]);
            qa[mi][kc][1] = __float_as_uint(r1[kc * 8 + t4]);
            qa[mi][kc][2] = __float_as_uint(r0[kc * 8 + t4 + 4]);
            qa[mi][kc][3] = __float_as_uint(r1[kc * 8 + t4 + 4]);
        }
    }

    float acc[2][8][4];
#pragma unroll
    for (int mi = 0; mi < 2; mi++)
#pragma unroll
        for (int en = 0; en < 8; en++)
#pragma unroll
            for (int r = 0; r < 4; r++) acc[mi][en][r] = 0.f;
    float rsum[2][2] = {{0.f, 0.f}, {0.f, 0.f}};

    const int sj = tid >> 1;
    const int sd = (tid & 1) * 32;
    const size_t abase = (size_t)(qb * 128 + w * 32) * N_NODES;

    for (int kb = 0; kb < 64; kb++) {
        __syncthreads();   // prior PV reads of k_s/v_s done
        {
            const float* kr = &g_k[(size_t)((kb << 6) + sj) * HD + hoff + sd];
#pragma unroll
            for (int c = 0; c < 8; c++) {
                float4 t = *(const float4*)(kr + c * 4);
                k_s[(sd + c * 4 + 0) * KP + sj] = t.x;
                k_s[(sd + c * 4 + 1) * KP + sj] = t.y;
                k_s[(sd + c * 4 + 2) * KP + sj] = t.z;
                k_s[(sd + c * 4 + 3) * KP + sj] = t.w;
            }
            const float* vr = &g_v[(size_t)((kb << 6) + sj) * HD + hoff + sd];
#pragma unroll
            for (int c = 0; c < 8; c++)
                *(float4*)&v_s[sj * KP + sd + c * 4] = *(const float4*)(vr + c * 4);
        }
        __syncthreads();

#pragma unroll 2
        for (int n = 0; n < 8; n++) {
            // adj loads for this 8-key tile (issued before S-mma to hide latency)
            const size_t acol = (size_t)(kb * 64 + n * 8 + 2 * t4);
            float2 a00 = *(const float2*)&adj[abase + (size_t)g * N_NODES + acol];
            float2 a01 = *(const float2*)&adj[abase + (size_t)(g + 8) * N_NODES + acol];
            float2 a10 = *(const float2*)&adj[abase + (size_t)(16 + g) * N_NODES + acol];
            float2 a11 = *(const float2*)&adj[abase + (size_t)(24 + g) * N_NODES + acol];

            // ---- S for this key tile ----
            float sc0[4] = {0.f, 0.f, 0.f, 0.f};
            float sc1[4] = {0.f, 0.f, 0.f, 0.f};
#pragma unroll
            for (int kc = 0; kc < 8; kc++) {
                unsigned b0 = __float_as_uint(k_s[(kc * 8 + t4) * KP + n * 8 + g]);
                unsigned b1 = __float_as_uint(k_s[(kc * 8 + t4 + 4) * KP + n * 8 + g]);
                mma_tf32(sc0, qa[0][kc], b0, b1);
                mma_tf32(sc1, qa[1][kc], b0, b1);
            }

            // ---- softmax numerator ----
            float p00 = fast_p(sc0[0], a00.x);
            float p01 = fast_p(sc0[1], a00.y);
            float p02 = fast_p(sc0[2], a01.x);
            float p03 = fast_p(sc0[3], a01.y);
            float p10 = fast_p(sc1[0], a10.x);
            float p11 = fast_p(sc1[1], a10.y);
            float p12 = fast_p(sc1[2], a11.x);
            float p13 = fast_p(sc1[3], a11.y);
            rsum[0][0] += p00 + p01;
            rsum[0][1] += p02 + p03;
            rsum[1][0] += p10 + p11;
            rsum[1][1] += p12 + p13;

            // ---- C-frag -> A-frag permutation via shuffles (4-lane groups) ----
            unsigned pa0[4], pa1[4];
            {
                float x, y;
                x = __shfl_sync(0xffffffffu, p00, s1);
                y = __shfl_sync(0xffffffffu, p01, s1);
                pa0[0] = __float_as_uint(odd ? y : x);
                x = __shfl_sync(0xffffffffu, p02, s1);
                y = __shfl_sync(0xffffffffu, p03, s1);
                pa0[1] = __float_as_uint(odd ? y : x);
                x = __shfl_sync(0xffffffffu, p00, s2);
                y = __shfl_sync(0xffffffffu, p01, s2);
                pa0[2] = __float_as_uint(odd ? y : x);
                x = __shfl_sync(0xffffffffu, p02, s2);
                y = __shfl_sync(0xffffffffu, p03, s2);
                pa0[3] = __float_as_uint(odd ? y : x);
                x = __shfl_sync(0xffffffffu, p10, s1);
                y = __shfl_sync(0xffffffffu, p11, s1);
                pa1[0] = __float_as_uint(odd ? y : x);
                x = __shfl_sync(0xffffffffu, p12, s1);
                y = __shfl_sync(0xffffffffu, p13, s1);
                pa1[1] = __float_as_uint(odd ? y : x);
                x = __shfl_sync(0xffffffffu, p10, s2);
                y = __shfl_sync(0xffffffffu, p11, s2);
                pa1[2] = __float_as_uint(odd ? y : x);
                x = __shfl_sync(0xffffffffu, p12, s2);
                y = __shfl_sync(0xffffffffu, p13, s2);
                pa1[3] = __float_as_uint(odd ? y : x);
            }

            // ---- PV for this key slab ----
#pragma unroll
            for (int en = 0; en < 8; en++) {
                unsigned b0 = __float_as_uint(v_s[(n * 8 + t4) * KP + en * 8 + g]);
                unsigned b1 = __float_as_uint(v_s[(n * 8 + t4 + 4) * KP + en * 8 + g]);
                mma_tf32(acc[0][en], pa0, b0, b1);
                mma_tf32(acc[1][en], pa1, b0, b1);
            }
        }
    }

    // ---- normalize and write out ----
    float inv[2][2];
#pragma unroll
    for (int mi = 0; mi < 2; mi++)
#pragma unroll
        for (int r = 0; r < 2; r++) {
            float s = rsum[mi][r];
            s += __shfl_xor_sync(0xffffffffu, s, 1);
            s += __shfl_xor_sync(0xffffffffu, s, 2);
            inv[mi][r] = __fdividef(1.f, s);
        }

#pragma unroll
    for (int mi = 0; mi < 2; mi++) {
        const int r0 = qrow0 + mi * 16 + g;
#pragma unroll
        for (int en = 0; en < 8; en++) {
            const int col = hoff + en * 8 + 2 * t4;
            *(float2*)&g_att[(size_t)r0 * HD + col] =
                make_float2(acc[mi][en][0] * inv[mi][0], acc[mi][en][1] * inv[mi][0]);
            *(float2*)&g_att[(size_t)(r0 + 8) * HD + col] =
                make_float2(acc[mi][en][2] * inv[mi][1], acc[mi][en][3] * inv[mi][1]);
        }
    }
}

// ---------------------------------------------------------------------------
// Output projection: out[4096,64] = g_att[4096,512] @ WO[512,64] + bO (fp32)
// ---------------------------------------------------------------------------
__global__ __launch_bounds__(256) void out_gemm(const float* __restrict__ WO,
                                                const float* __restrict__ bO,
                                                float* __restrict__ out) {
    __shared__ float As[32][68];
    __shared__ float Bs[32][68];
    const int tid = threadIdx.x;
    const int tx = tid & 15, ty = tid >> 4;
    const int bm = blockIdx.x * 64;

    float acc[4][4];
#pragma unroll
    for (int a = 0; a < 4; a++)
#pragma unroll
        for (int b = 0; b < 4; b++) acc[a][b] = 0.f;

    const int ar  = tid >> 2;
    const int akg = (tid & 3) * 8;
    const int bk  = tid >> 3;
    const int bjg = (tid & 7) * 8;

    for (int k0 = 0; k0 < HD; k0 += 32) {
        __syncthreads();
#pragma unroll
        for (int c = 0; c < 2; c++) {
            float4 v4 = *(const float4*)&g_att[(size_t)(bm + ar) * HD + k0 + akg + c * 4];
            As[akg + c * 4 + 0][ar] = v4.x;
            As[akg + c * 4 + 1][ar] = v4.y;
            As[akg + c * 4 + 2][ar] = v4.z;
            As[akg + c * 4 + 3][ar] = v4.w;
        }
#pragma unroll
        for (int c = 0; c < 2; c++)
            *(float4*)&Bs[bk][bjg + c * 4] =
                *(const float4*)&WO[(k0 + bk) * 64 + bjg + c * 4];
        __syncthreads();
#pragma unroll
        for (int kk = 0; kk < 32; kk++) {
            float4 a4 = *(float4*)&As[kk][ty * 4];
            float4 b4 = *(float4*)&Bs[kk][tx * 4];
            float arr[4] = {a4.x, a4.y, a4.z, a4.w};
            float brr[4] = {b4.x, b4.y, b4.z, b4.w};
#pragma unroll
            for (int a = 0; a < 4; a++)
#pragma unroll
                for (int b = 0; b < 4; b++) acc[a][b] += arr[a] * brr[b];
        }
    }

    float bl[4];
#pragma unroll
    for (int b = 0; b < 4; b++) bl[b] = bO[tx * 4 + b];
#pragma unroll
    for (int a = 0; a < 4; a++) {
        float4 o;
        o.x = acc[a][0] + bl[0];
        o.y = acc[a][1] + bl[1];
        o.z = acc[a][2] + bl[2];
        o.w = acc[a][3] + bl[3];
        *(float4*)&out[(size_t)(bm + ty * 4 + a) * 64 + tx * 4] = o;
    }
}

// ---------------------------------------------------------------------------
extern "C" void kernel_launch(void* const* d_in, const int* in_sizes, int n_in,
                              void* d_out, int out_size) {
    const float* Q   = (const float*)d_in[0];
    const float* K   = (const float*)d_in[1];
    const float* V   = (const float*)d_in[2];
    const float* adj = (const float*)d_in[3];
    const float* WQ  = (const float*)d_in[4];
    const float* bQ  = (const float*)d_in[5];
    const float* WK  = (const float*)d_in[6];
    const float* bK  = (const float*)d_in[7];
    const float* WV  = (const float*)d_in[8];
    const float* bV  = (const float*)d_in[9];
    const float* WO  = (const float*)d_in[10];
    const float* bO  = (const float*)d_in[11];
    float* out = (float*)d_out;

    float *qp, *kp, *vp;
    cudaGetSymbolAddress((void**)&qp, g_q);
    cudaGetSymbolAddress((void**)&kp, g_k);
    cudaGetSymbolAddress((void**)&vp, g_v);

    dim3 pgrid(HD / 128, N_NODES / 128);   // (4, 32)
    proj_mma<<<pgrid, 256>>>(Q, WQ, bQ, qp, 0.125f);  // q pre-scaled by d^-0.5
    proj_mma<<<pgrid, 256>>>(K, WK, bK, kp, 1.0f);
    proj_mma<<<pgrid, 256>>>(V, WV, bV, vp, 1.0f);

    attn_mma<<<dim3(32, 8), 128>>>(adj);

    out_gemm<<<N_NODES / 64, 256>>>(WO, bO, out);
}

// round 11
// speedup vs baseline: 1.0853x; 1.0853x over previous
#include <cuda_runtime.h>

#define N_NODES 4096
#define IN_DIM  512
#define HD      512   // H * ATT_DIM
#define ATT_DIM 64
#define NSPLIT  4     // key-dimension splits for attention
#define KB_PER_SPLIT (64 / NSPLIT)

// Scratch (device globals: allocation-free per harness rules)
__device__ float g_q[N_NODES * HD];
__device__ float g_k[N_NODES * HD];
__device__ float g_v[N_NODES * HD];
__device__ float g_att[N_NODES * HD];
__device__ float g_part[NSPLIT * N_NODES * HD];       // unnormalized PV partials
__device__ float g_rsum[NSPLIT * 8 * N_NODES];        // partial row sums [split][h][row]

// ---------------------------------------------------------------------------
// tf32 helpers
// ---------------------------------------------------------------------------
__device__ __forceinline__ unsigned f2tf(float f) {
    unsigned u;
    asm("cvt.rna.tf32.f32 %0, %1;" : "=r"(u) : "f"(f));
    return u;
}

// split x into hi (tf32) + lo (tf32 of remainder); hi+lo ~ 22-bit mantissa
__device__ __forceinline__ void tf32_split(float x, unsigned& hi, unsigned& lo) {
    hi = f2tf(x);
    lo = f2tf(x - __uint_as_float(hi));
}

__device__ __forceinline__ void mma_tf32(float c[4],
                                         const unsigned a[4],
                                         unsigned b0, unsigned b1) {
    asm volatile(
        "mma.sync.aligned.m16n8k8.row.col.f32.tf32.tf32.f32 "
        "{%0,%1,%2,%3}, {%4,%5,%6,%7}, {%8,%9}, {%0,%1,%2,%3};"
        : "+f"(c[0]), "+f"(c[1]), "+f"(c[2]), "+f"(c[3])
        : "r"(a[0]), "r"(a[1]), "r"(a[2]), "r"(a[3]), "r"(b0), "r"(b1));
}

// p = exp(sigmoid(s) + 0.1*a)   [the -0.5 bias is constant: cancels in softmax]
__device__ __forceinline__ float fast_p(float s, float a) {
    float e;
    asm("ex2.approx.f32 %0, %1;" : "=f"(e) : "f"(-1.442695041f * s));
    float r;
    asm("rcp.approx.f32 %0, %1;" : "=f"(r) : "f"(1.0f + e));
    float u = fmaf(0.1f, a, r - 0.55f);
    float p = fmaf(0.01444378f, u, 0.07221888f);
    p = fmaf(p, u, 0.28887550f);
    p = fmaf(p, u, 0.86662651f);
    p = fmaf(p, u, 1.73325302f);
    p = fmaf(p, u, 1.73325302f);
    return p;
}

// ---------------------------------------------------------------------------
// Projection GEMM via SPLIT-tf32 mma (fp32-grade accuracy), unchanged from R7.
// ---------------------------------------------------------------------------
__global__ __launch_bounds__(256) void proj_mma(const float* __restrict__ A,
                                                const float* __restrict__ W,
                                                const float* __restrict__ bias,
                                                float* __restrict__ C,
                                                float scale) {
    __shared__ float As[16 * 136];
    __shared__ float Bs[16 * 136];

    const int tid  = threadIdx.x;
    const int w    = tid >> 5;
    const int lane = tid & 31;
    const int g    = lane >> 2;
    const int t4   = lane & 3;
    const int m0   = (w >> 1) * 32;
    const int n0   = (w & 1) * 64;
    const int bm   = blockIdx.y * 128;
    const int bn   = blockIdx.x * 128;

    const int arow  = tid >> 1;
    const int ahalf = (tid & 1) * 8;
    const int aswz  = (ahalf & 8) << 1;
    const int brow  = tid >> 4;
    const int bcolg = (tid & 15) * 8;

    float acc[2][8][4];
#pragma unroll
    for (int mi = 0; mi < 2; mi++)
#pragma unroll
        for (int ni = 0; ni < 8; ni++)
#pragma unroll
            for (int r = 0; r < 4; r++) acc[mi][ni][r] = 0.f;

    for (int k0 = 0; k0 < IN_DIM; k0 += 16) {
        float4 av0 = *(const float4*)&A[(size_t)(bm + arow) * IN_DIM + k0 + ahalf];
        float4 av1 = *(const float4*)&A[(size_t)(bm + arow) * IN_DIM + k0 + ahalf + 4];
        float4 bv0 = *(const float4*)&W[(size_t)(k0 + brow) * HD + bn + bcolg];
        float4 bv1 = *(const float4*)&W[(size_t)(k0 + brow) * HD + bn + bcolg + 4];
        __syncthreads();
        {
            const int mi_ = arow ^ aswz;
            As[(ahalf + 0) * 136 + mi_] = av0.x;
            As[(ahalf + 1) * 136 + mi_] = av0.y;
            As[(ahalf + 2) * 136 + mi_] = av0.z;
            As[(ahalf + 3) * 136 + mi_] = av0.w;
            As[(ahalf + 4) * 136 + mi_] = av1.x;
            As[(ahalf + 5) * 136 + mi_] = av1.y;
            As[(ahalf + 6) * 136 + mi_] = av1.z;
            As[(ahalf + 7) * 136 + mi_] = av1.w;
            *(float4*)&Bs[brow * 136 + bcolg]     = bv0;
            *(float4*)&Bs[brow * 136 + bcolg + 4] = bv1;
        }
        __syncthreads();

#pragma unroll
        for (int s = 0; s < 2; s++) {
            const int swz = s << 4;
            unsigned ah[2][4], al[2][4];
#pragma unroll
            for (int mi = 0; mi < 2; mi++) {
                const int mrow = m0 + mi * 16 + g;
                tf32_split(As[(s * 8 + t4) * 136 + (mrow ^ swz)],        ah[mi][0], al[mi][0]);
                tf32_split(As[(s * 8 + t4) * 136 + ((mrow + 8) ^ swz)],  ah[mi][1], al[mi][1]);
                tf32_split(As[(s * 8 + t4 + 4) * 136 + (mrow ^ swz)],       ah[mi][2], al[mi][2]);
                tf32_split(As[(s * 8 + t4 + 4) * 136 + ((mrow + 8) ^ swz)], ah[mi][3], al[mi][3]);
            }
#pragma unroll
            for (int ni = 0; ni < 8; ni++) {
                unsigned bh0, bl0, bh1, bl1;
                tf32_split(Bs[(s * 8 + t4) * 136 + n0 + ni * 8 + g],     bh0, bl0);
                tf32_split(Bs[(s * 8 + t4 + 4) * 136 + n0 + ni * 8 + g], bh1, bl1);
#pragma unroll
                for (int mi = 0; mi < 2; mi++) {
                    mma_tf32(acc[mi][ni], ah[mi], bh0, bh1);  // hi*hi
                    mma_tf32(acc[mi][ni], ah[mi], bl0, bl1);  // hi*lo
                    mma_tf32(acc[mi][ni], al[mi], bh0, bh1);  // lo*hi
                }
            }
        }
    }

#pragma unroll
    for (int mi = 0; mi < 2; mi++) {
        const int r0 = bm + m0 + mi * 16 + g;
#pragma unroll
        for (int ni = 0; ni < 8; ni++) {
            const int col = bn + n0 + ni * 8 + 2 * t4;
            const float b0 = bias[col], b1 = bias[col + 1];
            float2 o0, o1;
            o0.x = __uint_as_float(f2tf((acc[mi][ni][0] + b0) * scale));
            o0.y = __uint_as_float(f2tf((acc[mi][ni][1] + b1) * scale));
            o1.x = __uint_as_float(f2tf((acc[mi][ni][2] + b0) * scale));
            o1.y = __uint_as_float(f2tf((acc[mi][ni][3] + b1) * scale));
            *(float2*)&C[(size_t)r0 * HD + col]       = o0;
            *(float2*)&C[(size_t)(r0 + 8) * HD + col] = o1;
        }
    }
}

// ---------------------------------------------------------------------------
// Attention, split-K over NSPLIT slabs of 1024 keys each.
// CTA = 128 queries x 1 head x 1 key slab; 4 warps x 32 rows.
// Writes UNNORMALIZED PV partials + partial row sums; reduce kernel combines.
// (valid because the streaming softmax uses no running max)
// ---------------------------------------------------------------------------
#define KP 72   // k_s/v_s pitch: 72 == 8 (mod 32) -> conflict-free B-frag reads

__global__ __launch_bounds__(128, 3) void attn_mma(const float* __restrict__ adj) {
    __shared__ float k_s[64 * KP];   // [d][j] transposed
    __shared__ float v_s[64 * KP];   // [j][e]

    const int tid  = threadIdx.x;
    const int w    = tid >> 5;
    const int lane = tid & 31;
    const int g    = lane >> 2;
    const int t4   = lane & 3;
    const int qb   = blockIdx.x;      // 0..31
    const int h    = blockIdx.y;      // 0..7
    const int zs   = blockIdx.z;      // 0..NSPLIT-1
    const int hoff = h * ATT_DIM;
    const int qrow0 = qb * 128 + w * 32;

    const int base = lane & 28;
    const int s1   = base + (t4 >> 1);
    const int s2   = s1 + 2;
    const bool odd = (t4 & 1);

    // q A-fragments resident in registers
    unsigned qa[2][8][4];
#pragma unroll
    for (int mi = 0; mi < 2; mi++) {
        const float* r0 = &g_q[(size_t)(qrow0 + mi * 16 + g) * HD + hoff];
        const float* r1 = &g_q[(size_t)(qrow0 + mi * 16 + g + 8) * HD + hoff];
#pragma unroll
        for (int kc = 0; kc < 8; kc++) {
            qa[mi][kc][0] = __float_as_uint(r0[kc * 8 + t4]);
            qa[mi][kc][1] = __float_as_uint(r1[kc * 8 + t4]);
            qa[mi][kc][2] = __float_as_uint(r0[kc * 8 + t4 + 4]);
            qa[mi][kc][3] = __float_as_uint(r1[kc * 8 + t4 + 4]);
        }
    }

    float acc[2][8][4];
#pragma unroll
    for (int mi = 0; mi < 2; mi++)
#pragma unroll
        for (int en = 0; en < 8; en++)
#pragma unroll
            for (int r = 0; r < 4; r++) acc[mi][en][r] = 0.f;
    float rsum[2][2] = {{0.f, 0.f}, {0.f, 0.f}};

    const int sj = tid >> 1;
    const int sd = (tid & 1) * 32;
    const size_t abase = (size_t)(qb * 128 + w * 32) * N_NODES;

    const int kb0 = zs * KB_PER_SPLIT;
    for (int kb = kb0; kb < kb0 + KB_PER_SPLIT; kb++) {
        __syncthreads();   // prior PV reads of k_s/v_s done
        {
            const float* kr = &g_k[(size_t)((kb << 6) + sj) * HD + hoff + sd];
#pragma unroll
            for (int c = 0; c < 8; c++) {
                float4 t = *(const float4*)(kr + c * 4);
                k_s[(sd + c * 4 + 0) * KP + sj] = t.x;
                k_s[(sd + c * 4 + 1) * KP + sj] = t.y;
                k_s[(sd + c * 4 + 2) * KP + sj] = t.z;
                k_s[(sd + c * 4 + 3) * KP + sj] = t.w;
            }
            const float* vr = &g_v[(size_t)((kb << 6) + sj) * HD + hoff + sd];
#pragma unroll
            for (int c = 0; c < 8; c++)
                *(float4*)&v_s[sj * KP + sd + c * 4] = *(const float4*)(vr + c * 4);
        }
        __syncthreads();

#pragma unroll 2
        for (int n = 0; n < 8; n++) {
            const size_t acol = (size_t)(kb * 64 + n * 8 + 2 * t4);
            float2 a00 = *(const float2*)&adj[abase + (size_t)g * N_NODES + acol];
            float2 a01 = *(const float2*)&adj[abase + (size_t)(g + 8) * N_NODES + acol];
            float2 a10 = *(const float2*)&adj[abase + (size_t)(16 + g) * N_NODES + acol];
            float2 a11 = *(const float2*)&adj[abase + (size_t)(24 + g) * N_NODES + acol];

            // ---- S for this key tile ----
            float sc0[4] = {0.f, 0.f, 0.f, 0.f};
            float sc1[4] = {0.f, 0.f, 0.f, 0.f};
#pragma unroll
            for (int kc = 0; kc < 8; kc++) {
                unsigned b0 = __float_as_uint(k_s[(kc * 8 + t4) * KP + n * 8 + g]);
                unsigned b1 = __float_as_uint(k_s[(kc * 8 + t4 + 4) * KP + n * 8 + g]);
                mma_tf32(sc0, qa[0][kc], b0, b1);
                mma_tf32(sc1, qa[1][kc], b0, b1);
            }

            // ---- softmax numerator ----
            float p00 = fast_p(sc0[0], a00.x);
            float p01 = fast_p(sc0[1], a00.y);
            float p02 = fast_p(sc0[2], a01.x);
            float p03 = fast_p(sc0[3], a01.y);
            float p10 = fast_p(sc1[0], a10.x);
            float p11 = fast_p(sc1[1], a10.y);
            float p12 = fast_p(sc1[2], a11.x);
            float p13 = fast_p(sc1[3], a11.y);
            rsum[0][0] += p00 + p01;
            rsum[0][1] += p02 + p03;
            rsum[1][0] += p10 + p11;
            rsum[1][1] += p12 + p13;

            // ---- C-frag -> A-frag permutation via shuffles ----
            unsigned pa0[4], pa1[4];
            {
                float x, y;
                x = __shfl_sync(0xffffffffu, p00, s1);
                y = __shfl_sync(0xffffffffu, p01, s1);
                pa0[0] = __float_as_uint(odd ? y : x);
                x = __shfl_sync(0xffffffffu, p02, s1);
                y = __shfl_sync(0xffffffffu, p03, s1);
                pa0[1] = __float_as_uint(odd ? y : x);
                x = __shfl_sync(0xffffffffu, p00, s2);
                y = __shfl_sync(0xffffffffu, p01, s2);
                pa0[2] = __float_as_uint(odd ? y : x);
                x = __shfl_sync(0xffffffffu, p02, s2);
                y = __shfl_sync(0xffffffffu, p03, s2);
                pa0[3] = __float_as_uint(odd ? y : x);
                x = __shfl_sync(0xffffffffu, p10, s1);
                y = __shfl_sync(0xffffffffu, p11, s1);
                pa1[0] = __float_as_uint(odd ? y : x);
                x = __shfl_sync(0xffffffffu, p12, s1);
                y = __shfl_sync(0xffffffffu, p13, s1);
                pa1[1] = __float_as_uint(odd ? y : x);
                x = __shfl_sync(0xffffffffu, p10, s2);
                y = __shfl_sync(0xffffffffu, p11, s2);
                pa1[2] = __float_as_uint(odd ? y : x);
                x = __shfl_sync(0xffffffffu, p12, s2);
                y = __shfl_sync(0xffffffffu, p13, s2);
                pa1[3] = __float_as_uint(odd ? y : x);
            }

            // ---- PV for this key slab ----
#pragma unroll
            for (int en = 0; en < 8; en++) {
                unsigned b0 = __float_as_uint(v_s[(n * 8 + t4) * KP + en * 8 + g]);
                unsigned b1 = __float_as_uint(v_s[(n * 8 + t4 + 4) * KP + en * 8 + g]);
                mma_tf32(acc[0][en], pa0, b0, b1);
                mma_tf32(acc[1][en], pa1, b0, b1);
            }
        }
    }

    // ---- partial row sums (reduce over t4) and unnormalized store ----
#pragma unroll
    for (int mi = 0; mi < 2; mi++)
#pragma unroll
        for (int r = 0; r < 2; r++) {
            float s = rsum[mi][r];
            s += __shfl_xor_sync(0xffffffffu, s, 1);
            s += __shfl_xor_sync(0xffffffffu, s, 2);
            rsum[mi][r] = s;
        }
    if (t4 == 0) {
        float* rp = &g_rsum[(size_t)(zs * 8 + h) * N_NODES];
        rp[qrow0 + g]      = rsum[0][0];
        rp[qrow0 + g + 8]  = rsum[0][1];
        rp[qrow0 + g + 16] = rsum[1][0];
        rp[qrow0 + g + 24] = rsum[1][1];
    }

    float* part = &g_part[(size_t)zs * N_NODES * HD];
#pragma unroll
    for (int mi = 0; mi < 2; mi++) {
        const int r0 = qrow0 + mi * 16 + g;
#pragma unroll
        for (int en = 0; en < 8; en++) {
            const int col = hoff + en * 8 + 2 * t4;
            *(float2*)&part[(size_t)r0 * HD + col] =
                make_float2(acc[mi][en][0], acc[mi][en][1]);
            *(float2*)&part[(size_t)(r0 + 8) * HD + col] =
                make_float2(acc[mi][en][2], acc[mi][en][3]);
        }
    }
}

// ---------------------------------------------------------------------------
// Combine split-K partials: g_att = (sum parts) / (sum rsums)
// One float4 per thread; 4096*512/4/256 = 2048 blocks.
// ---------------------------------------------------------------------------
__global__ __launch_bounds__(256) void attn_reduce() {
    const int idx = blockIdx.x * 256 + threadIdx.x;   // float4 index
    const int row = idx >> 7;                         // 128 float4 per row
    const int col = (idx & 127) << 2;
    const int h   = col >> 6;

    float rs = 0.f;
#pragma unroll
    for (int z = 0; z < NSPLIT; z++)
        rs += g_rsum[(size_t)(z * 8 + h) * N_NODES + row];

    float4 s = make_float4(0.f, 0.f, 0.f, 0.f);
#pragma unroll
    for (int z = 0; z < NSPLIT; z++) {
        float4 p = *(const float4*)&g_part[((size_t)z * N_NODES + row) * HD + col];
        s.x += p.x; s.y += p.y; s.z += p.z; s.w += p.w;
    }
    const float inv = __fdividef(1.f, rs);
    s.x *= inv; s.y *= inv; s.z *= inv; s.w *= inv;
    *(float4*)&g_att[(size_t)row * HD + col] = s;
}

// ---------------------------------------------------------------------------
// Output projection: out[4096,64] = g_att[4096,512] @ WO[512,64] + bO (fp32)
// ---------------------------------------------------------------------------
__global__ __launch_bounds__(256) void out_gemm(const float* __restrict__ WO,
                                                const float* __restrict__ bO,
                                                float* __restrict__ out) {
    __shared__ float As[32][68];
    __shared__ float Bs[32][68];
    const int tid = threadIdx.x;
    const int tx = tid & 15, ty = tid >> 4;
    const int bm = blockIdx.x * 64;

    float acc[4][4];
#pragma unroll
    for (int a = 0; a < 4; a++)
#pragma unroll
        for (int b = 0; b < 4; b++) acc[a][b] = 0.f;

    const int ar  = tid >> 2;
    const int akg = (tid & 3) * 8;
    const int bk  = tid >> 3;
    const int bjg = (tid & 7) * 8;

    for (int k0 = 0; k0 < HD; k0 += 32) {
        __syncthreads();
#pragma unroll
        for (int c = 0; c < 2; c++) {
            float4 v4 = *(const float4*)&g_att[(size_t)(bm + ar) * HD + k0 + akg + c * 4];
            As[akg + c * 4 + 0][ar] = v4.x;
            As[akg + c * 4 + 1][ar] = v4.y;
            As[akg + c * 4 + 2][ar] = v4.z;
            As[akg + c * 4 + 3][ar] = v4.w;
        }
#pragma unroll
        for (int c = 0; c < 2; c++)
            *(float4*)&Bs[bk][bjg + c * 4] =
                *(const float4*)&WO[(k0 + bk) * 64 + bjg + c * 4];
        __syncthreads();
#pragma unroll
        for (int kk = 0; kk < 32; kk++) {
            float4 a4 = *(float4*)&As[kk][ty * 4];
            float4 b4 = *(float4*)&Bs[kk][tx * 4];
            float arr[4] = {a4.x, a4.y, a4.z, a4.w};
            float brr[4] = {b4.x, b4.y, b4.z, b4.w};
#pragma unroll
            for (int a = 0; a < 4; a++)
#pragma unroll
                for (int b = 0; b < 4; b++) acc[a][b] += arr[a] * brr[b];
        }
    }

    float bl[4];
#pragma unroll
    for (int b = 0; b < 4; b++) bl[b] = bO[tx * 4 + b];
#pragma unroll
    for (int a = 0; a < 4; a++) {
        float4 o;
        o.x = acc[a][0] + bl[0];
        o.y = acc[a][1] + bl[1];
        o.z = acc[a][2] + bl[2];
        o.w = acc[a][3] + bl[3];
        *(float4*)&out[(size_t)(bm + ty * 4 + a) * 64 + tx * 4] = o;
    }
}

// ---------------------------------------------------------------------------
extern "C" void kernel_launch(void* const* d_in, const int* in_sizes, int n_in,
                              void* d_out, int out_size) {
    const float* Q   = (const float*)d_in[0];
    const float* K   = (const float*)d_in[1];
    const float* V   = (const float*)d_in[2];
    const float* adj = (const float*)d_in[3];
    const float* WQ  = (const float*)d_in[4];
    const float* bQ  = (const float*)d_in[5];
    const float* WK  = (const float*)d_in[6];
    const float* bK  = (const float*)d_in[7];
    const float* WV  = (const float*)d_in[8];
    const float* bV  = (const float*)d_in[9];
    const float* WO  = (const float*)d_in[10];
    const float* bO  = (const float*)d_in[11];
    float* out = (float*)d_out;

    float *qp, *kp, *vp;
    cudaGetSymbolAddress((void**)&qp, g_q);
    cudaGetSymbolAddress((void**)&kp, g_k);
    cudaGetSymbolAddress((void**)&vp, g_v);

    dim3 pgrid(HD / 128, N_NODES / 128);   // (4, 32)
    proj_mma<<<pgrid, 256>>>(Q, WQ, bQ, qp, 0.125f);  // q pre-scaled by d^-0.5
    proj_mma<<<pgrid, 256>>>(K, WK, bK, kp, 1.0f);
    proj_mma<<<pgrid, 256>>>(V, WV, bV, vp, 1.0f);

    attn_mma<<<dim3(32, 8, NSPLIT), 128>>>(adj);
    attn_reduce<<<(N_NODES * HD / 4) / 256, 256>>>();

    out_gemm<<<N_NODES / 64, 256>>>(WO, bO, out);
}

// round 12
// speedup vs baseline: 1.1869x; 1.0936x over previous
#include <cuda_runtime.h>

#define N_NODES 4096
#define IN_DIM  512
#define HD      512   // H * ATT_DIM
#define ATT_DIM 64
#define NSPLIT  4     // key-dimension splits for attention
#define KB_PER_SPLIT (64 / NSPLIT)

// Scratch (device globals: allocation-free per harness rules)
__device__ float g_q[N_NODES * HD];
__device__ float g_k[N_NODES * HD];
__device__ float g_v[N_NODES * HD];
__device__ float g_att[N_NODES * HD];
__device__ float g_part[NSPLIT * N_NODES * HD];       // unnormalized PV partials
__device__ float g_rsum[NSPLIT * 8 * N_NODES];        // partial row sums [split][h][row]

// ---------------------------------------------------------------------------
// tf32 / async helpers
// ---------------------------------------------------------------------------
__device__ __forceinline__ unsigned f2tf(float f) {
    unsigned u;
    asm("cvt.rna.tf32.f32 %0, %1;" : "=r"(u) : "f"(f));
    return u;
}

__device__ __forceinline__ void tf32_split(float x, unsigned& hi, unsigned& lo) {
    hi = f2tf(x);
    lo = f2tf(x - __uint_as_float(hi));
}

__device__ __forceinline__ void mma_tf32(float c[4],
                                         const unsigned a[4],
                                         unsigned b0, unsigned b1) {
    asm volatile(
        "mma.sync.aligned.m16n8k8.row.col.f32.tf32.tf32.f32 "
        "{%0,%1,%2,%3}, {%4,%5,%6,%7}, {%8,%9}, {%0,%1,%2,%3};"
        : "+f"(c[0]), "+f"(c[1]), "+f"(c[2]), "+f"(c[3])
        : "r"(a[0]), "r"(a[1]), "r"(a[2]), "r"(a[3]), "r"(b0), "r"(b1));
}

__device__ __forceinline__ void cp16(unsigned smem_dst, const void* gptr) {
    asm volatile("cp.async.cg.shared.global [%0], [%1], 16;"
                 :: "r"(smem_dst), "l"(gptr));
}

// p = exp(sigmoid(s) + 0.1*a)   [the -0.5 bias is constant: cancels in softmax]
__device__ __forceinline__ float fast_p(float s, float a) {
    float e;
    asm("ex2.approx.f32 %0, %1;" : "=f"(e) : "f"(-1.442695041f * s));
    float r;
    asm("rcp.approx.f32 %0, %1;" : "=f"(r) : "f"(1.0f + e));
    float u = fmaf(0.1f, a, r - 0.55f);
    float p = fmaf(0.01444378f, u, 0.07221888f);
    p = fmaf(p, u, 0.28887550f);
    p = fmaf(p, u, 0.86662651f);
    p = fmaf(p, u, 1.73325302f);
    p = fmaf(p, u, 1.73325302f);
    return p;
}

// ---------------------------------------------------------------------------
// Fused projection GEMMs via SPLIT-tf32 mma (fp32-grade accuracy).
// blockIdx.z selects (Q,WQ,bQ)->g_q (scaled), (K,WK,bK)->g_k, (V,WV,bV)->g_v.
// One launch = 384 CTAs: better SM fill than 3x128.
// ---------------------------------------------------------------------------
__global__ __launch_bounds__(256) void proj_mma(
        const float* __restrict__ Qi, const float* __restrict__ Ki,
        const float* __restrict__ Vi,
        const float* __restrict__ WQ, const float* __restrict__ WK,
        const float* __restrict__ WV,
        const float* __restrict__ bQ, const float* __restrict__ bK,
        const float* __restrict__ bV,
        float* __restrict__ qp, float* __restrict__ kp, float* __restrict__ vp) {
    __shared__ float As[16 * 136];
    __shared__ float Bs[16 * 136];

    const int z = blockIdx.z;
    const float* A    = (z == 0) ? Qi : (z == 1) ? Ki : Vi;
    const float* W    = (z == 0) ? WQ : (z == 1) ? WK : WV;
    const float* bias = (z == 0) ? bQ : (z == 1) ? bK : bV;
    float*       C    = (z == 0) ? qp : (z == 1) ? kp : vp;
    const float scale = (z == 0) ? 0.125f : 1.0f;   // q pre-scaled by d^-0.5

    const int tid  = threadIdx.x;
    const int w    = tid >> 5;
    const int lane = tid & 31;
    const int g    = lane >> 2;
    const int t4   = lane & 3;
    const int m0   = (w >> 1) * 32;
    const int n0   = (w & 1) * 64;
    const int bm   = blockIdx.y * 128;
    const int bn   = blockIdx.x * 128;

    const int arow  = tid >> 1;
    const int ahalf = (tid & 1) * 8;
    const int aswz  = (ahalf & 8) << 1;
    const int brow  = tid >> 4;
    const int bcolg = (tid & 15) * 8;

    float acc[2][8][4];
#pragma unroll
    for (int mi = 0; mi < 2; mi++)
#pragma unroll
        for (int ni = 0; ni < 8; ni++)
#pragma unroll
            for (int r = 0; r < 4; r++) acc[mi][ni][r] = 0.f;

    for (int k0 = 0; k0 < IN_DIM; k0 += 16) {
        float4 av0 = *(const float4*)&A[(size_t)(bm + arow) * IN_DIM + k0 + ahalf];
        float4 av1 = *(const float4*)&A[(size_t)(bm + arow) * IN_DIM + k0 + ahalf + 4];
        float4 bv0 = *(const float4*)&W[(size_t)(k0 + brow) * HD + bn + bcolg];
        float4 bv1 = *(const float4*)&W[(size_t)(k0 + brow) * HD + bn + bcolg + 4];
        __syncthreads();
        {
            const int mi_ = arow ^ aswz;
            As[(ahalf + 0) * 136 + mi_] = av0.x;
            As[(ahalf + 1) * 136 + mi_] = av0.y;
            As[(ahalf + 2) * 136 + mi_] = av0.z;
            As[(ahalf + 3) * 136 + mi_] = av0.w;
            As[(ahalf + 4) * 136 + mi_] = av1.x;
            As[(ahalf + 5) * 136 + mi_] = av1.y;
            As[(ahalf + 6) * 136 + mi_] = av1.z;
            As[(ahalf + 7) * 136 + mi_] = av1.w;
            *(float4*)&Bs[brow * 136 + bcolg]     = bv0;
            *(float4*)&Bs[brow * 136 + bcolg + 4] = bv1;
        }
        __syncthreads();

#pragma unroll
        for (int s = 0; s < 2; s++) {
            const int swz = s << 4;
            unsigned ah[2][4], al[2][4];
#pragma unroll
            for (int mi = 0; mi < 2; mi++) {
                const int mrow = m0 + mi * 16 + g;
                tf32_split(As[(s * 8 + t4) * 136 + (mrow ^ swz)],        ah[mi][0], al[mi][0]);
                tf32_split(As[(s * 8 + t4) * 136 + ((mrow + 8) ^ swz)],  ah[mi][1], al[mi][1]);
                tf32_split(As[(s * 8 + t4 + 4) * 136 + (mrow ^ swz)],       ah[mi][2], al[mi][2]);
                tf32_split(As[(s * 8 + t4 + 4) * 136 + ((mrow + 8) ^ swz)], ah[mi][3], al[mi][3]);
            }
#pragma unroll
            for (int ni = 0; ni < 8; ni++) {
                unsigned bh0, bl0, bh1, bl1;
                tf32_split(Bs[(s * 8 + t4) * 136 + n0 + ni * 8 + g],     bh0, bl0);
                tf32_split(Bs[(s * 8 + t4 + 4) * 136 + n0 + ni * 8 + g], bh1, bl1);
#pragma unroll
                for (int mi = 0; mi < 2; mi++) {
                    mma_tf32(acc[mi][ni], ah[mi], bh0, bh1);  // hi*hi
                    mma_tf32(acc[mi][ni], ah[mi], bl0, bl1);  // hi*lo
                    mma_tf32(acc[mi][ni], al[mi], bh0, bh1);  // lo*hi
                }
            }
        }
    }

#pragma unroll
    for (int mi = 0; mi < 2; mi++) {
        const int r0 = bm + m0 + mi * 16 + g;
#pragma unroll
        for (int ni = 0; ni < 8; ni++) {
            const int col = bn + n0 + ni * 8 + 2 * t4;
            const float b0 = bias[col], b1 = bias[col + 1];
            float2 o0, o1;
            o0.x = __uint_as_float(f2tf((acc[mi][ni][0] + b0) * scale));
            o0.y = __uint_as_float(f2tf((acc[mi][ni][1] + b1) * scale));
            o1.x = __uint_as_float(f2tf((acc[mi][ni][2] + b0) * scale));
            o1.y = __uint_as_float(f2tf((acc[mi][ni][3] + b1) * scale));
            *(float2*)&C[(size_t)r0 * HD + col]       = o0;
            *(float2*)&C[(size_t)(r0 + 8) * HD + col] = o1;
        }
    }
}

// ---------------------------------------------------------------------------
// Attention, split-K, cp.async double-buffered k/v staging (both ROW-major:
// k pitch 68 -> S B-frag banks 4g+t4 conflict-free, staging (l+c)%8 cf;
// v pitch 76 -> PV B-frag banks 12t4+g conflict-free, staging (3l+c)%8 cf).
// S accumulation split into even/odd-kc chains (depth 8 -> 4).
// adj prefetched one n-tile ahead.
// ---------------------------------------------------------------------------
#define KPk 68
#define KPv 76
#define BUF_WORDS (64 * KPk + 64 * KPv)       // 9216 words = 36864 B
#define ATT_SMEM  (2 * BUF_WORDS * 4)          // 73728 B (double buffer)

__global__ __launch_bounds__(128, 3) void attn_mma(const float* __restrict__ adj) {
    extern __shared__ float sbuf[];
    const unsigned sbase = (unsigned)__cvta_generic_to_shared(sbuf);

    const int tid  = threadIdx.x;
    const int w    = tid >> 5;
    const int lane = tid & 31;
    const int g    = lane >> 2;
    const int t4   = lane & 3;
    const int qb   = blockIdx.x;      // 0..31
    const int h    = blockIdx.y;      // 0..7
    const int zs   = blockIdx.z;      // 0..NSPLIT-1
    const int hoff = h * ATT_DIM;
    const int qrow0 = qb * 128 + w * 32;

    const int base = lane & 28;
    const int s1   = base + (t4 >> 1);
    const int s2   = s1 + 2;
    const bool odd = (t4 & 1);

    // staging map: thread -> (row, col-half); conflict-free for both pitches
    const int sjj = tid & 63;
    const int sch = (tid >> 6) * 32;
    const int kb0 = zs * KB_PER_SPLIT;

    // prologue: stage kb0 into buffer 0
    {
        const float* kr = &g_k[(size_t)((kb0 << 6) + sjj) * HD + hoff + sch];
        const float* vr = &g_v[(size_t)((kb0 << 6) + sjj) * HD + hoff + sch];
        unsigned kd = sbase + (sjj * KPk + sch) * 4;
        unsigned vd = sbase + (64 * KPk + sjj * KPv + sch) * 4;
#pragma unroll
        for (int c = 0; c < 8; c++) cp16(kd + c * 16, kr + c * 4);
#pragma unroll
        for (int c = 0; c < 8; c++) cp16(vd + c * 16, vr + c * 4);
        asm volatile("cp.async.commit_group;" ::: "memory");
    }

    // q A-fragments resident in registers
    unsigned qa[2][8][4];
#pragma unroll
    for (int mi = 0; mi < 2; mi++) {
        const float* r0 = &g_q[(size_t)(qrow0 + mi * 16 + g) * HD + hoff];
        const float* r1 = &g_q[(size_t)(qrow0 + mi * 16 + g + 8) * HD + hoff];
#pragma unroll
        for (int kc = 0; kc < 8; kc++) {
            qa[mi][kc][0] = __float_as_uint(r0[kc * 8 + t4]);
            qa[mi][kc][1] = __float_as_uint(r1[kc * 8 + t4]);
            qa[mi][kc][2] = __float_as_uint(r0[kc * 8 + t4 + 4]);
            qa[mi][kc][3] = __float_as_uint(r1[kc * 8 + t4 + 4]);
        }
    }

    float acc[2][8][4];
#pragma unroll
    for (int mi = 0; mi < 2; mi++)
#pragma unroll
        for (int en = 0; en < 8; en++)
#pragma unroll
            for (int r = 0; r < 4; r++) acc[mi][en][r] = 0.f;
    float rsum[2][2] = {{0.f, 0.f}, {0.f, 0.f}};

    const size_t abase = (size_t)(qb * 128 + w * 32) * N_NODES;

    for (int i = 0; i < KB_PER_SPLIT; i++) {
        const int kb = kb0 + i;
        const int b  = i & 1;
        // stage next kb into the other buffer; wait for current
        if (i + 1 < KB_PER_SPLIT) {
            const float* kr = &g_k[(size_t)(((kb + 1) << 6) + sjj) * HD + hoff + sch];
            const float* vr = &g_v[(size_t)(((kb + 1) << 6) + sjj) * HD + hoff + sch];
            unsigned kd = sbase + ((b ^ 1) * BUF_WORDS + sjj * KPk + sch) * 4;
            unsigned vd = sbase + ((b ^ 1) * BUF_WORDS + 64 * KPk + sjj * KPv + sch) * 4;
#pragma unroll
            for (int c = 0; c < 8; c++) cp16(kd + c * 16, kr + c * 4);
#pragma unroll
            for (int c = 0; c < 8; c++) cp16(vd + c * 16, vr + c * 4);
            asm volatile("cp.async.commit_group;" ::: "memory");
            asm volatile("cp.async.wait_group 1;" ::: "memory");
        } else {
            asm volatile("cp.async.wait_group 0;" ::: "memory");
        }
        __syncthreads();   // current buffer visible to all warps

        const float* k_s = sbuf + b * BUF_WORDS;
        const float* v_s = k_s + 64 * KPk;

        // adj for n=0 (current), then prefetch n+1 each iteration
        float2 a00, a01, a10, a11;
        {
            const size_t acol = (size_t)(kb * 64 + 2 * t4);
            a00 = *(const float2*)&adj[abase + (size_t)g * N_NODES + acol];
            a01 = *(const float2*)&adj[abase + (size_t)(g + 8) * N_NODES + acol];
            a10 = *(const float2*)&adj[abase + (size_t)(16 + g) * N_NODES + acol];
            a11 = *(const float2*)&adj[abase + (size_t)(24 + g) * N_NODES + acol];
        }

#pragma unroll 2
        for (int n = 0; n < 8; n++) {
            float2 b00, b01, b10, b11;
            if (n < 7) {
                const size_t acol = (size_t)(kb * 64 + (n + 1) * 8 + 2 * t4);
                b00 = *(const float2*)&adj[abase + (size_t)g * N_NODES + acol];
                b01 = *(const float2*)&adj[abase + (size_t)(g + 8) * N_NODES + acol];
                b10 = *(const float2*)&adj[abase + (size_t)(16 + g) * N_NODES + acol];
                b11 = *(const float2*)&adj[abase + (size_t)(24 + g) * N_NODES + acol];
            }

            // ---- S for this key tile: even/odd kc chains (depth 4 each) ----
            float sc0[4] = {0.f, 0.f, 0.f, 0.f};
            float sc1[4] = {0.f, 0.f, 0.f, 0.f};
            float sc0b[4] = {0.f, 0.f, 0.f, 0.f};
            float sc1b[4] = {0.f, 0.f, 0.f, 0.f};
            const float* krow = k_s + (n * 8 + g) * KPk;
#pragma unroll
            for (int kc = 0; kc < 4; kc++) {
                unsigned e0 = __float_as_uint(krow[(2 * kc) * 8 + t4]);
                unsigned e1 = __float_as_uint(krow[(2 * kc) * 8 + t4 + 4]);
                unsigned o0 = __float_as_uint(krow[(2 * kc + 1) * 8 + t4]);
                unsigned o1 = __float_as_uint(krow[(2 * kc + 1) * 8 + t4 + 4]);
                mma_tf32(sc0,  qa[0][2 * kc],     e0, e1);
                mma_tf32(sc1,  qa[1][2 * kc],     e0, e1);
                mma_tf32(sc0b, qa[0][2 * kc + 1], o0, o1);
                mma_tf32(sc1b, qa[1][2 * kc + 1], o0, o1);
            }
#pragma unroll
            for (int r = 0; r < 4; r++) { sc0[r] += sc0b[r]; sc1[r] += sc1b[r]; }

            // ---- softmax numerator ----
            float p00 = fast_p(sc0[0], a00.x);
            float p01 = fast_p(sc0[1], a00.y);
            float p02 = fast_p(sc0[2], a01.x);
            float p03 = fast_p(sc0[3], a01.y);
            float p10 = fast_p(sc1[0], a10.x);
            float p11 = fast_p(sc1[1], a10.y);
            float p12 = fast_p(sc1[2], a11.x);
            float p13 = fast_p(sc1[3], a11.y);
            rsum[0][0] += p00 + p01;
            rsum[0][1] += p02 + p03;
            rsum[1][0] += p10 + p11;
            rsum[1][1] += p12 + p13;
            a00 = b00; a01 = b01; a10 = b10; a11 = b11;

            // ---- C-frag -> A-frag permutation via shuffles ----
            unsigned pa0[4], pa1[4];
            {
                float x, y;
                x = __shfl_sync(0xffffffffu, p00, s1);
                y = __shfl_sync(0xffffffffu, p01, s1);
                pa0[0] = __float_as_uint(odd ? y : x);
                x = __shfl_sync(0xffffffffu, p02, s1);
                y = __shfl_sync(0xffffffffu, p03, s1);
                pa0[1] = __float_as_uint(odd ? y : x);
                x = __shfl_sync(0xffffffffu, p00, s2);
                y = __shfl_sync(0xffffffffu, p01, s2);
                pa0[2] = __float_as_uint(odd ? y : x);
                x = __shfl_sync(0xffffffffu, p02, s2);
                y = __shfl_sync(0xffffffffu, p03, s2);
                pa0[3] = __float_as_uint(odd ? y : x);
                x = __shfl_sync(0xffffffffu, p10, s1);
                y = __shfl_sync(0xffffffffu, p11, s1);
                pa1[0] = __float_as_uint(odd ? y : x);
                x = __shfl_sync(0xffffffffu, p12, s1);
                y = __shfl_sync(0xffffffffu, p13, s1);
                pa1[1] = __float_as_uint(odd ? y : x);
                x = __shfl_sync(0xffffffffu, p10, s2);
                y = __shfl_sync(0xffffffffu, p11, s2);
                pa1[2] = __float_as_uint(odd ? y : x);
                x = __shfl_sync(0xffffffffu, p12, s2);
                y = __shfl_sync(0xffffffffu, p13, s2);
                pa1[3] = __float_as_uint(odd ? y : x);
            }

            // ---- PV for this key slab ----
            const float* vrow0 = v_s + (n * 8 + t4) * KPv;
            const float* vrow1 = v_s + (n * 8 + t4 + 4) * KPv;
#pragma unroll
            for (int en = 0; en < 8; en++) {
                unsigned b0 = __float_as_uint(vrow0[en * 8 + g]);
                unsigned b1 = __float_as_uint(vrow1[en * 8 + g]);
                mma_tf32(acc[0][en], pa0, b0, b1);
                mma_tf32(acc[1][en], pa1, b0, b1);
            }
        }
        __syncthreads();   // all warps done reading buffer b before refill
    }

    // ---- partial row sums (reduce over t4) and unnormalized store ----
#pragma unroll
    for (int mi = 0; mi < 2; mi++)
#pragma unroll
        for (int r = 0; r < 2; r++) {
            float s = rsum[mi][r];
            s += __shfl_xor_sync(0xffffffffu, s, 1);
            s += __shfl_xor_sync(0xffffffffu, s, 2);
            rsum[mi][r] = s;
        }
    if (t4 == 0) {
        float* rp = &g_rsum[(size_t)(zs * 8 + h) * N_NODES];
        rp[qrow0 + g]      = rsum[0][0];
        rp[qrow0 + g + 8]  = rsum[0][1];
        rp[qrow0 + g + 16] = rsum[1][0];
        rp[qrow0 + g + 24] = rsum[1][1];
    }

    float* part = &g_part[(size_t)zs * N_NODES * HD];
#pragma unroll
    for (int mi = 0; mi < 2; mi++) {
        const int r0 = qrow0 + mi * 16 + g;
#pragma unroll
        for (int en = 0; en < 8; en++) {
            const int col = hoff + en * 8 + 2 * t4;
            *(float2*)&part[(size_t)r0 * HD + col] =
                make_float2(acc[0 * 0 + mi][en][0], acc[mi][en][1]);
            *(float2*)&part[(size_t)(r0 + 8) * HD + col] =
                make_float2(acc[mi][en][2], acc[mi][en][3]);
        }
    }
}

// ---------------------------------------------------------------------------
// Combine split-K partials: g_att = (sum parts) / (sum rsums)
// ---------------------------------------------------------------------------
__global__ __launch_bounds__(256) void attn_reduce() {
    const int idx = blockIdx.x * 256 + threadIdx.x;   // float4 index
    const int row = idx >> 7;                         // 128 float4 per row
    const int col = (idx & 127) << 2;
    const int h   = col >> 6;

    float rs = 0.f;
#pragma unroll
    for (int z = 0; z < NSPLIT; z++)
        rs += g_rsum[(size_t)(z * 8 + h) * N_NODES + row];

    float4 s = make_float4(0.f, 0.f, 0.f, 0.f);
#pragma unroll
    for (int z = 0; z < NSPLIT; z++) {
        float4 p = *(const float4*)&g_part[((size_t)z * N_NODES + row) * HD + col];
        s.x += p.x; s.y += p.y; s.z += p.z; s.w += p.w;
    }
    const float inv = __fdividef(1.f, rs);
    s.x *= inv; s.y *= inv; s.z *= inv; s.w *= inv;
    *(float4*)&g_att[(size_t)row * HD + col] = s;
}

// ---------------------------------------------------------------------------
// Output projection: out[4096,64] = g_att[4096,512] @ WO[512,64] + bO (fp32)
// ---------------------------------------------------------------------------
__global__ __launch_bounds__(256) void out_gemm(const float* __restrict__ WO,
                                                const float* __restrict__ bO,
                                                float* __restrict__ out) {
    __shared__ float As[32][68];
    __shared__ float Bs[32][68];
    const int tid = threadIdx.x;
    const int tx = tid & 15, ty = tid >> 4;
    const int bm = blockIdx.x * 64;

    float acc[4][4];
#pragma unroll
    for (int a = 0; a < 4; a++)
#pragma unroll
        for (int b = 0; b < 4; b++) acc[a][b] = 0.f;

    const int ar  = tid >> 2;
    const int akg = (tid & 3) * 8;
    const int bk  = tid >> 3;
    const int bjg = (tid & 7) * 8;

    for (int k0 = 0; k0 < HD; k0 += 32) {
        __syncthreads();
#pragma unroll
        for (int c = 0; c < 2; c++) {
            float4 v4 = *(const float4*)&g_att[(size_t)(bm + ar) * HD + k0 + akg + c * 4];
            As[akg + c * 4 + 0][ar] = v4.x;
            As[akg + c * 4 + 1][ar] = v4.y;
            As[akg + c * 4 + 2][ar] = v4.z;
            As[akg + c * 4 + 3][ar] = v4.w;
        }
#pragma unroll
        for (int c = 0; c < 2; c++)
            *(float4*)&Bs[bk][bjg + c * 4] =
                *(const float4*)&WO[(k0 + bk) * 64 + bjg + c * 4];
        __syncthreads();
#pragma unroll
        for (int kk = 0; kk < 32; kk++) {
            float4 a4 = *(float4*)&As[kk][ty * 4];
            float4 b4 = *(float4*)&Bs[kk][tx * 4];
            float arr[4] = {a4.x, a4.y, a4.z, a4.w};
            float brr[4] = {b4.x, b4.y, b4.z, b4.w};
#pragma unroll
            for (int a = 0; a < 4; a++)
#pragma unroll
                for (int b = 0; b < 4; b++) acc[a][b] += arr[a] * brr[b];
        }
    }

    float bl[4];
#pragma unroll
    for (int b = 0; b < 4; b++) bl[b] = bO[tx * 4 + b];
#pragma unroll
    for (int a = 0; a < 4; a++) {
        float4 o;
        o.x = acc[a][0] + bl[0];
        o.y = acc[a][1] + bl[1];
        o.z = acc[a][2] + bl[2];
        o.w = acc[a][3] + bl[3];
        *(float4*)&out[(size_t)(bm + ty * 4 + a) * 64 + tx * 4] = o;
    }
}

// ---------------------------------------------------------------------------
extern "C" void kernel_launch(void* const* d_in, const int* in_sizes, int n_in,
                              void* d_out, int out_size) {
    const float* Q   = (const float*)d_in[0];
    const float* K   = (const float*)d_in[1];
    const float* V   = (const float*)d_in[2];
    const float* adj = (const float*)d_in[3];
    const float* WQ  = (const float*)d_in[4];
    const float* bQ  = (const float*)d_in[5];
    const float* WK  = (const float*)d_in[6];
    const float* bK  = (const float*)d_in[7];
    const float* WV  = (const float*)d_in[8];
    const float* bV  = (const float*)d_in[9];
    const float* WO  = (const float*)d_in[10];
    const float* bO  = (const float*)d_in[11];
    float* out = (float*)d_out;

    float *qp, *kp, *vp;
    cudaGetSymbolAddress((void**)&qp, g_q);
    cudaGetSymbolAddress((void**)&kp, g_k);
    cudaGetSymbolAddress((void**)&vp, g_v);

    proj_mma<<<dim3(HD / 128, N_NODES / 128, 3), 256>>>(
        Q, K, V, WQ, WK, WV, bQ, bK, bV, qp, kp, vp);

    cudaFuncSetAttribute(attn_mma,
                         cudaFuncAttributeMaxDynamicSharedMemorySize, ATT_SMEM);
    attn_mma<<<dim3(32, 8, NSPLIT), 128, ATT_SMEM>>>(adj);
    attn_reduce<<<(N_NODES * HD / 4) / 256, 256>>>();

    out_gemm<<<N_NODES / 64, 256>>>(WO, bO, out);
}

// round 13
// speedup vs baseline: 1.3633x; 1.1487x over previous
#include <cuda_runtime.h>
#include <cuda_fp16.h>

#define N_NODES 4096
#define IN_DIM  512
#define HD      512   // H * ATT_DIM
#define ATT_DIM 64
#define NSPLIT  4     // key-dimension splits for attention
#define KB_PER_SPLIT (64 / NSPLIT)

// Scratch (device globals: allocation-free per harness rules)
__device__ float  g_q[N_NODES * HD];
__device__ float  g_k[N_NODES * HD];
__device__ float  g_v[N_NODES * HD];
__device__ __half g_vt[8 * ATT_DIM * N_NODES];        // V fp16 transposed [h][e][j]
__device__ float  g_att[N_NODES * HD];
__device__ float  g_part[NSPLIT * N_NODES * HD];      // unnormalized PV partials
__device__ float  g_rsum[NSPLIT * 8 * N_NODES];       // partial row sums [split][h][row]

// ---------------------------------------------------------------------------
// tf32 / fp16 / async helpers
// ---------------------------------------------------------------------------
__device__ __forceinline__ unsigned f2tf(float f) {
    unsigned u;
    asm("cvt.rna.tf32.f32 %0, %1;" : "=r"(u) : "f"(f));
    return u;
}

__device__ __forceinline__ void tf32_split(float x, unsigned& hi, unsigned& lo) {
    hi = f2tf(x);
    lo = f2tf(x - __uint_as_float(hi));
}

__device__ __forceinline__ void mma_tf32(float c[4],
                                         const unsigned a[4],
                                         unsigned b0, unsigned b1) {
    asm volatile(
        "mma.sync.aligned.m16n8k8.row.col.f32.tf32.tf32.f32 "
        "{%0,%1,%2,%3}, {%4,%5,%6,%7}, {%8,%9}, {%0,%1,%2,%3};"
        : "+f"(c[0]), "+f"(c[1]), "+f"(c[2]), "+f"(c[3])
        : "r"(a[0]), "r"(a[1]), "r"(a[2]), "r"(a[3]), "r"(b0), "r"(b1));
}

__device__ __forceinline__ void mma_f16(float c[4],
                                        unsigned a0, unsigned a1,
                                        unsigned a2, unsigned a3,
                                        unsigned b0, unsigned b1) {
    asm volatile(
        "mma.sync.aligned.m16n8k16.row.col.f32.f16.f16.f32 "
        "{%0,%1,%2,%3}, {%4,%5,%6,%7}, {%8,%9}, {%0,%1,%2,%3};"
        : "+f"(c[0]), "+f"(c[1]), "+f"(c[2]), "+f"(c[3])
        : "r"(a0), "r"(a1), "r"(a2), "r"(a3), "r"(b0), "r"(b1));
}

__device__ __forceinline__ unsigned packh2(float lo, float hi) {
    __half2 h = __floats2half2_rn(lo, hi);   // .x = lo (low 16 bits)
    return *(unsigned*)&h;
}

__device__ __forceinline__ void cp16(unsigned smem_dst, const void* gptr) {
    asm volatile("cp.async.cg.shared.global [%0], [%1], 16;"
                 :: "r"(smem_dst), "l"(gptr));
}

// p = exp(sigmoid(s) + 0.1*a)   [the -0.5 bias is constant: cancels in softmax]
__device__ __forceinline__ float fast_p(float s, float a) {
    float e;
    asm("ex2.approx.f32 %0, %1;" : "=f"(e) : "f"(-1.442695041f * s));
    float r;
    asm("rcp.approx.f32 %0, %1;" : "=f"(r) : "f"(1.0f + e));
    float u = fmaf(0.1f, a, r - 0.55f);
    float p = fmaf(0.01444378f, u, 0.07221888f);
    p = fmaf(p, u, 0.28887550f);
    p = fmaf(p, u, 0.86662651f);
    p = fmaf(p, u, 1.73325302f);
    p = fmaf(p, u, 1.73325302f);
    return p;
}

// ---------------------------------------------------------------------------
// Fused projection GEMMs via SPLIT-tf32 mma (fp32-grade accuracy). Unchanged.
// ---------------------------------------------------------------------------
__global__ __launch_bounds__(256) void proj_mma(
        const float* __restrict__ Qi, const float* __restrict__ Ki,
        const float* __restrict__ Vi,
        const float* __restrict__ WQ, const float* __restrict__ WK,
        const float* __restrict__ WV,
        const float* __restrict__ bQ, const float* __restrict__ bK,
        const float* __restrict__ bV,
        float* __restrict__ qp, float* __restrict__ kp, float* __restrict__ vp) {
    __shared__ float As[16 * 136];
    __shared__ float Bs[16 * 136];

    const int z = blockIdx.z;
    const float* A    = (z == 0) ? Qi : (z == 1) ? Ki : Vi;
    const float* W    = (z == 0) ? WQ : (z == 1) ? WK : WV;
    const float* bias = (z == 0) ? bQ : (z == 1) ? bK : bV;
    float*       C    = (z == 0) ? qp : (z == 1) ? kp : vp;
    const float scale = (z == 0) ? 0.125f : 1.0f;   // q pre-scaled by d^-0.5

    const int tid  = threadIdx.x;
    const int w    = tid >> 5;
    const int lane = tid & 31;
    const int g    = lane >> 2;
    const int t4   = lane & 3;
    const int m0   = (w >> 1) * 32;
    const int n0   = (w & 1) * 64;
    const int bm   = blockIdx.y * 128;
    const int bn   = blockIdx.x * 128;

    const int arow  = tid >> 1;
    const int ahalf = (tid & 1) * 8;
    const int aswz  = (ahalf & 8) << 1;
    const int brow  = tid >> 4;
    const int bcolg = (tid & 15) * 8;

    float acc[2][8][4];
#pragma unroll
    for (int mi = 0; mi < 2; mi++)
#pragma unroll
        for (int ni = 0; ni < 8; ni++)
#pragma unroll
            for (int r = 0; r < 4; r++) acc[mi][ni][r] = 0.f;

    for (int k0 = 0; k0 < IN_DIM; k0 += 16) {
        float4 av0 = *(const float4*)&A[(size_t)(bm + arow) * IN_DIM + k0 + ahalf];
        float4 av1 = *(const float4*)&A[(size_t)(bm + arow) * IN_DIM + k0 + ahalf + 4];
        float4 bv0 = *(const float4*)&W[(size_t)(k0 + brow) * HD + bn + bcolg];
        float4 bv1 = *(const float4*)&W[(size_t)(k0 + brow) * HD + bn + bcolg + 4];
        __syncthreads();
        {
            const int mi_ = arow ^ aswz;
            As[(ahalf + 0) * 136 + mi_] = av0.x;
            As[(ahalf + 1) * 136 + mi_] = av0.y;
            As[(ahalf + 2) * 136 + mi_] = av0.z;
            As[(ahalf + 3) * 136 + mi_] = av0.w;
            As[(ahalf + 4) * 136 + mi_] = av1.x;
            As[(ahalf + 5) * 136 + mi_] = av1.y;
            As[(ahalf + 6) * 136 + mi_] = av1.z;
            As[(ahalf + 7) * 136 + mi_] = av1.w;
            *(float4*)&Bs[brow * 136 + bcolg]     = bv0;
            *(float4*)&Bs[brow * 136 + bcolg + 4] = bv1;
        }
        __syncthreads();

#pragma unroll
        for (int s = 0; s < 2; s++) {
            const int swz = s << 4;
            unsigned ah[2][4], al[2][4];
#pragma unroll
            for (int mi = 0; mi < 2; mi++) {
                const int mrow = m0 + mi * 16 + g;
                tf32_split(As[(s * 8 + t4) * 136 + (mrow ^ swz)],        ah[mi][0], al[mi][0]);
                tf32_split(As[(s * 8 + t4) * 136 + ((mrow + 8) ^ swz)],  ah[mi][1], al[mi][1]);
                tf32_split(As[(s * 8 + t4 + 4) * 136 + (mrow ^ swz)],       ah[mi][2], al[mi][2]);
                tf32_split(As[(s * 8 + t4 + 4) * 136 + ((mrow + 8) ^ swz)], ah[mi][3], al[mi][3]);
            }
#pragma unroll
            for (int ni = 0; ni < 8; ni++) {
                unsigned bh0, bl0, bh1, bl1;
                tf32_split(Bs[(s * 8 + t4) * 136 + n0 + ni * 8 + g],     bh0, bl0);
                tf32_split(Bs[(s * 8 + t4 + 4) * 136 + n0 + ni * 8 + g], bh1, bl1);
#pragma unroll
                for (int mi = 0; mi < 2; mi++) {
                    mma_tf32(acc[mi][ni], ah[mi], bh0, bh1);  // hi*hi
                    mma_tf32(acc[mi][ni], ah[mi], bl0, bl1);  // hi*lo
                    mma_tf32(acc[mi][ni], al[mi], bh0, bh1);  // lo*hi
                }
            }
        }
    }

#pragma unroll
    for (int mi = 0; mi < 2; mi++) {
        const int r0 = bm + m0 + mi * 16 + g;
#pragma unroll
        for (int ni = 0; ni < 8; ni++) {
            const int col = bn + n0 + ni * 8 + 2 * t4;
            const float b0 = bias[col], b1 = bias[col + 1];
            float2 o0, o1;
            o0.x = __uint_as_float(f2tf((acc[mi][ni][0] + b0) * scale));
            o0.y = __uint_as_float(f2tf((acc[mi][ni][1] + b1) * scale));
            o1.x = __uint_as_float(f2tf((acc[mi][ni][2] + b0) * scale));
            o1.y = __uint_as_float(f2tf((acc[mi][ni][3] + b1) * scale));
            *(float2*)&C[(size_t)r0 * HD + col]       = o0;
            *(float2*)&C[(size_t)(r0 + 8) * HD + col] = o1;
        }
    }
}

// ---------------------------------------------------------------------------
// V transpose to fp16: g_vt[h][e][j] = (half)g_v[j][h*64+e].
// 64j x 64e tile per CTA via smem. ~12MB traffic, a few us.
// ---------------------------------------------------------------------------
__global__ __launch_bounds__(256) void v_trans() {
    __shared__ __half ts[64 * 72];
    const int tid = threadIdx.x;
    const int j0  = blockIdx.x * 64;
    const int h   = blockIdx.y;

    const int col4 = tid & 15;         // 0..15 (float4 within row)
    const int jr   = tid >> 4;         // 0..15
#pragma unroll
    for (int c = 0; c < 4; c++) {
        const int j = jr + 16 * c;
        float4 v4 = *(const float4*)&g_v[(size_t)(j0 + j) * HD + h * 64 + col4 * 4];
        __half2* d = (__half2*)&ts[j * 72 + col4 * 4];
        d[0] = __floats2half2_rn(v4.x, v4.y);
        d[1] = __floats2half2_rn(v4.z, v4.w);
    }
    __syncthreads();

    const int e0 = tid >> 3;           // 0..31
    const int jc = tid & 7;            // 8-half chunk
#pragma unroll
    for (int c = 0; c < 2; c++) {
        const int e = e0 + 32 * c;
        __half tmp[8];
#pragma unroll
        for (int i = 0; i < 8; i++) tmp[i] = ts[(jc * 8 + i) * 72 + e];
        *(uint4*)&g_vt[((size_t)(h * 64 + e)) * N_NODES + j0 + jc * 8] = *(uint4*)tmp;
    }
}

// ---------------------------------------------------------------------------
// Attention, split-K, cp.async double-buffered k (fp32) + vt (fp16) staging.
// Per 16-key group: two tf32 S-tiles -> softmax -> pack half2 (C-frag IS the
// fp16 m16n8k16 A-frag: NO shuffles) -> one fp16 PV mma per (en, mi).
// ---------------------------------------------------------------------------
#define KPk 68                                   // k pitch (words): 4g+t4 cf
#define VPH 72                                   // vt pitch (halves): 4g+t4 cf
#define BUF_WORDS (64 * KPk + 64 * (VPH / 2))    // 6656 words = 26624 B
#define ATT_SMEM  (2 * BUF_WORDS * 4)            // 53248 B (double buffer)

__global__ __launch_bounds__(128, 3) void attn_mma(const float* __restrict__ adj) {
    extern __shared__ float sbuf[];
    const unsigned sbase = (unsigned)__cvta_generic_to_shared(sbuf);

    const int tid  = threadIdx.x;
    const int w    = tid >> 5;
    const int lane = tid & 31;
    const int g    = lane >> 2;
    const int t4   = lane & 3;
    const int qb   = blockIdx.x;      // 0..31
    const int h    = blockIdx.y;      // 0..7
    const int zs   = blockIdx.z;      // 0..NSPLIT-1
    const int hoff = h * ATT_DIM;
    const int qrow0 = qb * 128 + w * 32;

    // staging maps
    const int sjj = tid & 63;                    // k: row
    const int sch = (tid >> 6) * 32;             // k: col half
    const int sve = tid >> 1;                    // v: e row
    const int svh = (tid & 1) * 32;              // v: half offset in row
    const int kb0 = zs * KB_PER_SPLIT;
    const __half* vt = &g_vt[(size_t)hoff * N_NODES];

    // prologue: stage kb0 into buffer 0
    {
        const float* kr = &g_k[(size_t)((kb0 << 6) + sjj) * HD + hoff + sch];
        unsigned kd = sbase + (sjj * KPk + sch) * 4;
#pragma unroll
        for (int c = 0; c < 8; c++) cp16(kd + c * 16, kr + c * 4);
        const __half* vr = &vt[(size_t)sve * N_NODES + (kb0 << 6) + svh];
        unsigned vd = sbase + 64 * KPk * 4 + (sve * VPH + svh) * 2;
#pragma unroll
        for (int c = 0; c < 4; c++) cp16(vd + c * 16, vr + c * 8);
        asm volatile("cp.async.commit_group;" ::: "memory");
    }

    // q A-fragments resident in registers
    unsigned qa[2][8][4];
#pragma unroll
    for (int mi = 0; mi < 2; mi++) {
        const float* r0 = &g_q[(size_t)(qrow0 + mi * 16 + g) * HD + hoff];
        const float* r1 = &g_q[(size_t)(qrow0 + mi * 16 + g + 8) * HD + hoff];
#pragma unroll
        for (int kc = 0; kc < 8; kc++) {
            qa[mi][kc][0] = __float_as_uint(r0[kc * 8 + t4]);
            qa[mi][kc][1] = __float_as_uint(r1[kc * 8 + t4]);
            qa[mi][kc][2] = __float_as_uint(r0[kc * 8 + t4 + 4]);
            qa[mi][kc][3] = __float_as_uint(r1[kc * 8 + t4 + 4]);
        }
    }

    float acc[2][8][4];
#pragma unroll
    for (int mi = 0; mi < 2; mi++)
#pragma unroll
        for (int en = 0; en < 8; en++)
#pragma unroll
            for (int r = 0; r < 4; r++) acc[mi][en][r] = 0.f;
    float rsum[2][2] = {{0.f, 0.f}, {0.f, 0.f}};

    const size_t abase = (size_t)(qb * 128 + w * 32) * N_NODES;

    for (int i = 0; i < KB_PER_SPLIT; i++) {
        const int kb = kb0 + i;
        const int b  = i & 1;
        if (i + 1 < KB_PER_SPLIT) {
            const float* kr = &g_k[(size_t)(((kb + 1) << 6) + sjj) * HD + hoff + sch];
            unsigned kd = sbase + ((b ^ 1) * BUF_WORDS + sjj * KPk + sch) * 4;
#pragma unroll
            for (int c = 0; c < 8; c++) cp16(kd + c * 16, kr + c * 4);
            const __half* vr = &vt[(size_t)sve * N_NODES + ((kb + 1) << 6) + svh];
            unsigned vd = sbase + ((b ^ 1) * BUF_WORDS + 64 * KPk) * 4 + (sve * VPH + svh) * 2;
#pragma unroll
            for (int c = 0; c < 4; c++) cp16(vd + c * 16, vr + c * 8);
            asm volatile("cp.async.commit_group;" ::: "memory");
            asm volatile("cp.async.wait_group 1;" ::: "memory");
        } else {
            asm volatile("cp.async.wait_group 0;" ::: "memory");
        }
        __syncthreads();

        const float*  k_s = sbuf + b * BUF_WORDS;
        const __half* v_h = (const __half*)(k_s + 64 * KPk);

#pragma unroll
        for (int n2 = 0; n2 < 4; n2++) {
            // adj for both 8-key tiles of this 16-key group (batch-issued)
            const size_t cA = (size_t)(kb * 64 + n2 * 16 + 2 * t4);
            float2 aA0 = *(const float2*)&adj[abase + (size_t)g * N_NODES + cA];
            float2 aA1 = *(const float2*)&adj[abase + (size_t)(g + 8) * N_NODES + cA];
            float2 aA2 = *(const float2*)&adj[abase + (size_t)(16 + g) * N_NODES + cA];
            float2 aA3 = *(const float2*)&adj[abase + (size_t)(24 + g) * N_NODES + cA];
            float2 aB0 = *(const float2*)&adj[abase + (size_t)g * N_NODES + cA + 8];
            float2 aB1 = *(const float2*)&adj[abase + (size_t)(g + 8) * N_NODES + cA + 8];
            float2 aB2 = *(const float2*)&adj[abase + (size_t)(16 + g) * N_NODES + cA + 8];
            float2 aB3 = *(const float2*)&adj[abase + (size_t)(24 + g) * N_NODES + cA + 8];

            // ---- S for the two 8-key tiles (4 independent mma chains) ----
            float sA0[4] = {0.f, 0.f, 0.f, 0.f};
            float sA1[4] = {0.f, 0.f, 0.f, 0.f};
            float sB0[4] = {0.f, 0.f, 0.f, 0.f};
            float sB1[4] = {0.f, 0.f, 0.f, 0.f};
            const float* krA = k_s + (n2 * 16 + g) * KPk;
            const float* krB = krA + 8 * KPk;
#pragma unroll
            for (int kc = 0; kc < 8; kc++) {
                unsigned eA0 = __float_as_uint(krA[kc * 8 + t4]);
                unsigned eA1 = __float_as_uint(krA[kc * 8 + t4 + 4]);
                unsigned eB0 = __float_as_uint(krB[kc * 8 + t4]);
                unsigned eB1 = __float_as_uint(krB[kc * 8 + t4 + 4]);
                mma_tf32(sA0, qa[0][kc], eA0, eA1);
                mma_tf32(sA1, qa[1][kc], eA0, eA1);
                mma_tf32(sB0, qa[0][kc], eB0, eB1);
                mma_tf32(sB1, qa[1][kc], eB0, eB1);
            }

            // ---- softmax numerators (fp32) ----
            float pA00 = fast_p(sA0[0], aA0.x), pA01 = fast_p(sA0[1], aA0.y);
            float pA02 = fast_p(sA0[2], aA1.x), pA03 = fast_p(sA0[3], aA1.y);
            float pA10 = fast_p(sA1[0], aA2.x), pA11 = fast_p(sA1[1], aA2.y);
            float pA12 = fast_p(sA1[2], aA3.x), pA13 = fast_p(sA1[3], aA3.y);
            float pB00 = fast_p(sB0[0], aB0.x), pB01 = fast_p(sB0[1], aB0.y);
            float pB02 = fast_p(sB0[2], aB1.x), pB03 = fast_p(sB0[3], aB1.y);
            float pB10 = fast_p(sB1[0], aB2.x), pB11 = fast_p(sB1[1], aB2.y);
            float pB12 = fast_p(sB1[2], aB3.x), pB13 = fast_p(sB1[3], aB3.y);
            rsum[0][0] += pA00 + pA01 + pB00 + pB01;
            rsum[0][1] += pA02 + pA03 + pB02 + pB03;
            rsum[1][0] += pA10 + pA11 + pB10 + pB11;
            rsum[1][1] += pA12 + pA13 + pB12 + pB13;

            // ---- pack: S C-frags ARE the fp16 m16n8k16 A-frag (no shuffles) ----
            unsigned a0m0 = packh2(pA00, pA01), a1m0 = packh2(pA02, pA03);
            unsigned a2m0 = packh2(pB00, pB01), a3m0 = packh2(pB02, pB03);
            unsigned a0m1 = packh2(pA10, pA11), a1m1 = packh2(pA12, pA13);
            unsigned a2m1 = packh2(pB10, pB11), a3m1 = packh2(pB12, pB13);

            // ---- PV: fp16 m16n8k16, V^T[e][j] half2 loads ----
#pragma unroll
            for (int en = 0; en < 8; en++) {
                const __half* vrow = v_h + (en * 8 + g) * VPH + n2 * 16;
                unsigned b0 = *(const unsigned*)(vrow + 2 * t4);
                unsigned b1 = *(const unsigned*)(vrow + 2 * t4 + 8);
                mma_f16(acc[0][en], a0m0, a1m0, a2m0, a3m0, b0, b1);
                mma_f16(acc[1][en], a0m1, a1m1, a2m1, a3m1, b0, b1);
            }
        }
        __syncthreads();   // all warps done reading buffer b before refill
    }

    // ---- partial row sums (reduce over t4) and unnormalized store ----
#pragma unroll
    for (int mi = 0; mi < 2; mi++)
#pragma unroll
        for (int r = 0; r < 2; r++) {
            float s = rsum[mi][r];
            s += __shfl_xor_sync(0xffffffffu, s, 1);
            s += __shfl_xor_sync(0xffffffffu, s, 2);
            rsum[mi][r] = s;
        }
    if (t4 == 0) {
        float* rp = &g_rsum[(size_t)(zs * 8 + h) * N_NODES];
        rp[qrow0 + g]      = rsum[0][0];
        rp[qrow0 + g + 8]  = rsum[0][1];
        rp[qrow0 + g + 16] = rsum[1][0];
        rp[qrow0 + g + 24] = rsum[1][1];
    }

    float* part = &g_part[(size_t)zs * N_NODES * HD];
#pragma unroll
    for (int mi = 0; mi < 2; mi++) {
        const int r0 = qrow0 + mi * 16 + g;
#pragma unroll
        for (int en = 0; en < 8; en++) {
            const int col = hoff + en * 8 + 2 * t4;
            *(float2*)&part[(size_t)r0 * HD + col] =
                make_float2(acc[mi][en][0], acc[mi][en][1]);
            *(float2*)&part[(size_t)(r0 + 8) * HD + col] =
                make_float2(acc[mi][en][2], acc[mi][en][3]);
        }
    }
}

// ---------------------------------------------------------------------------
// Combine split-K partials: g_att = (sum parts) / (sum rsums)
// ---------------------------------------------------------------------------
__global__ __launch_bounds__(256) void attn_reduce() {
    const int idx = blockIdx.x * 256 + threadIdx.x;   // float4 index
    const int row = idx >> 7;
    const int col = (idx & 127) << 2;
    const int h   = col >> 6;

    float rs = 0.f;
#pragma unroll
    for (int z = 0; z < NSPLIT; z++)
        rs += g_rsum[(size_t)(z * 8 + h) * N_NODES + row];

    float4 s = make_float4(0.f, 0.f, 0.f, 0.f);
#pragma unroll
    for (int z = 0; z < NSPLIT; z++) {
        float4 p = *(const float4*)&g_part[((size_t)z * N_NODES + row) * HD + col];
        s.x += p.x; s.y += p.y; s.z += p.z; s.w += p.w;
    }
    const float inv = __fdividef(1.f, rs);
    s.x *= inv; s.y *= inv; s.z *= inv; s.w *= inv;
    *(float4*)&g_att[(size_t)row * HD + col] = s;
}

// ---------------------------------------------------------------------------
// Output projection: out[4096,64] = g_att[4096,512] @ WO[512,64] + bO (fp32)
// BM=32 -> 128 CTAs (was 64: half the chip idle).
// ---------------------------------------------------------------------------
__global__ __launch_bounds__(256) void out_gemm(const float* __restrict__ WO,
                                                const float* __restrict__ bO,
                                                float* __restrict__ out) {
    __shared__ float As[32 * 36];
    __shared__ float Bs[32 * 68];
    const int tid = threadIdx.x;
    const int tx = tid & 15, ty = tid >> 4;
    const int bm = blockIdx.x * 32;

    float acc[2][4];
#pragma unroll
    for (int a = 0; a < 2; a++)
#pragma unroll
        for (int b = 0; b < 4; b++) acc[a][b] = 0.f;

    const int ar  = tid >> 3;          // 0..31
    const int akg = (tid & 7) * 4;     // k group
    const int bk  = tid >> 3;          // 0..31
    const int bjg = (tid & 7) * 8;

    for (int k0 = 0; k0 < HD; k0 += 32) {
        __syncthreads();
        {
            float4 a4 = *(const float4*)&g_att[(size_t)(bm + ar) * HD + k0 + akg];
            As[(akg + 0) * 36 + ar] = a4.x;
            As[(akg + 1) * 36 + ar] = a4.y;
            As[(akg + 2) * 36 + ar] = a4.z;
            As[(akg + 3) * 36 + ar] = a4.w;
        }
#pragma unroll
        for (int c = 0; c < 2; c++)
            *(float4*)&Bs[bk * 68 + bjg + c * 4] =
                *(const float4*)&WO[(k0 + bk) * 64 + bjg + c * 4];
        __syncthreads();
#pragma unroll
        for (int kk = 0; kk < 32; kk++) {
            float a0 = As[kk * 36 + ty * 2];
            float a1 = As[kk * 36 + ty * 2 + 1];
            float4 b4 = *(float4*)&Bs[kk * 68 + tx * 4];
            float brr[4] = {b4.x, b4.y, b4.z, b4.w};
#pragma unroll
            for (int b = 0; b < 4; b++) {
                acc[0][b] += a0 * brr[b];
                acc[1][b] += a1 * brr[b];
            }
        }
    }

    float bl[4];
#pragma unroll
    for (int b = 0; b < 4; b++) bl[b] = bO[tx * 4 + b];
#pragma unroll
    for (int a = 0; a < 2; a++) {
        float4 o;
        o.x = acc[a][0] + bl[0];
        o.y = acc[a][1] + bl[1];
        o.z = acc[a][2] + bl[2];
        o.w = acc[a][3] + bl[3];
        *(float4*)&out[(size_t)(bm + ty * 2 + a) * 64 + tx * 4] = o;
    }
}

// ---------------------------------------------------------------------------
extern "C" void kernel_launch(void* const* d_in, const int* in_sizes, int n_in,
                              void* d_out, int out_size) {
    const float* Q   = (const float*)d_in[0];
    const float* K   = (const float*)d_in[1];
    const float* V   = (const float*)d_in[2];
    const float* adj = (const float*)d_in[3];
    const float* WQ  = (const float*)d_in[4];
    const float* bQ  = (const float*)d_in[5];
    const float* WK  = (const float*)d_in[6];
    const float* bK  = (const float*)d_in[7];
    const float* WV  = (const float*)d_in[8];
    const float* bV  = (const float*)d_in[9];
    const float* WO  = (const float*)d_in[10];
    const float* bO  = (const float*)d_in[11];
    float* out = (float*)d_out;

    float *qp, *kp, *vp;
    cudaGetSymbolAddress((void**)&qp, g_q);
    cudaGetSymbolAddress((void**)&kp, g_k);
    cudaGetSymbolAddress((void**)&vp, g_v);

    proj_mma<<<dim3(HD / 128, N_NODES / 128, 3), 256>>>(
        Q, K, V, WQ, WK, WV, bQ, bK, bV, qp, kp, vp);

    v_trans<<<dim3(N_NODES / 64, 8), 256>>>();

    cudaFuncSetAttribute(attn_mma,
                         cudaFuncAttributeMaxDynamicSharedMemorySize, ATT_SMEM);
    attn_mma<<<dim3(32, 8, NSPLIT), 128, ATT_SMEM>>>(adj);
    attn_reduce<<<(N_NODES * HD / 4) / 256, 256>>>();

    out_gemm<<<N_NODES / 32, 256>>>(WO, bO, out);
}

// round 17
// speedup vs baseline: 1.9193x; 1.4078x over previous
#include <cuda_runtime.h>
#include <cuda_fp16.h>

#define N_NODES 4096
#define IN_DIM  512
#define HD      512   // H * ATT_DIM
#define ATT_DIM 64
#define NSPLIT  8     // key-dimension splits for attention
#define KB_PER_SPLIT (64 / NSPLIT)

// Scratch (device globals: allocation-free per harness rules)
__device__ __half g_qh[N_NODES * HD];                 // q fp16 (pre-scaled)
__device__ __half g_kh[N_NODES * HD];                 // k fp16
__device__ float  g_v[N_NODES * HD];
__device__ __half g_vt[8 * ATT_DIM * N_NODES];        // V fp16 transposed [h][e][j]
__device__ float  g_att[N_NODES * HD];
__device__ float  g_part[NSPLIT * N_NODES * HD];      // unnormalized PV partials
__device__ float  g_rsum[NSPLIT * 8 * N_NODES];       // partial row sums [split][h][row]

// ---------------------------------------------------------------------------
// tf32 / fp16 / async helpers
// ---------------------------------------------------------------------------
__device__ __forceinline__ unsigned f2tf(float f) {
    unsigned u;
    asm("cvt.rna.tf32.f32 %0, %1;" : "=r"(u) : "f"(f));
    return u;
}

__device__ __forceinline__ void tf32_split(float x, unsigned& hi, unsigned& lo) {
    hi = f2tf(x);
    lo = f2tf(x - __uint_as_float(hi));
}

__device__ __forceinline__ void mma_tf32(float c[4],
                                         const unsigned a[4],
                                         unsigned b0, unsigned b1) {
    asm volatile(
        "mma.sync.aligned.m16n8k8.row.col.f32.tf32.tf32.f32 "
        "{%0,%1,%2,%3}, {%4,%5,%6,%7}, {%8,%9}, {%0,%1,%2,%3};"
        : "+f"(c[0]), "+f"(c[1]), "+f"(c[2]), "+f"(c[3])
        : "r"(a[0]), "r"(a[1]), "r"(a[2]), "r"(a[3]), "r"(b0), "r"(b1));
}

__device__ __forceinline__ void mma_f16(float c[4],
                                        unsigned a0, unsigned a1,
                                        unsigned a2, unsigned a3,
                                        unsigned b0, unsigned b1) {
    asm volatile(
        "mma.sync.aligned.m16n8k16.row.col.f32.f16.f16.f32 "
        "{%0,%1,%2,%3}, {%4,%5,%6,%7}, {%8,%9}, {%0,%1,%2,%3};"
        : "+f"(c[0]), "+f"(c[1]), "+f"(c[2]), "+f"(c[3])
        : "r"(a0), "r"(a1), "r"(a2), "r"(a3), "r"(b0), "r"(b1));
}

__device__ __forceinline__ unsigned packh2(float lo, float hi) {
    __half2 h = __floats2half2_rn(lo, hi);   // .x = lo (low 16 bits)
    return *(unsigned*)&h;
}

__device__ __forceinline__ void cp16(unsigned smem_dst, const void* gptr) {
    asm volatile("cp.async.cg.shared.global [%0], [%1], 16;"
                 :: "r"(smem_dst), "l"(gptr));
}

// p = exp(sigmoid(s) + 0.1*a)   [the -0.5 bias is constant: cancels in softmax]
__device__ __forceinline__ float fast_p(float s, float a) {
    float e;
    asm("ex2.approx.f32 %0, %1;" : "=f"(e) : "f"(-1.442695041f * s));
    float r;
    asm("rcp.approx.f32 %0, %1;" : "=f"(r) : "f"(1.0f + e));
    float u = fmaf(0.1f, a, r - 0.55f);
    float p = fmaf(0.01444378f, u, 0.07221888f);
    p = fmaf(p, u, 0.28887550f);
    p = fmaf(p, u, 0.86662651f);
    p = fmaf(p, u, 1.73325302f);
    p = fmaf(p, u, 1.73325302f);
    return p;
}

// ---------------------------------------------------------------------------
// Fused projection GEMMs via SPLIT-tf32 mma (fp32-grade accuracy).
// z=0 -> q fp16 (scaled by d^-0.5), z=1 -> k fp16, z=2 -> v fp32.
// ---------------------------------------------------------------------------
__global__ __launch_bounds__(256) void proj_mma(
        const float* __restrict__ Qi, const float* __restrict__ Ki,
        const float* __restrict__ Vi,
        const float* __restrict__ WQ, const float* __restrict__ WK,
        const float* __restrict__ WV,
        const float* __restrict__ bQ, const float* __restrict__ bK,
        const float* __restrict__ bV,
        __half* __restrict__ qp, __half* __restrict__ kp,
        float* __restrict__ vp) {
    __shared__ float As[16 * 136];
    __shared__ float Bs[16 * 136];

    const int z = blockIdx.z;
    const float* A    = (z == 0) ? Qi : (z == 1) ? Ki : Vi;
    const float* W    = (z == 0) ? WQ : (z == 1) ? WK : WV;
    const float* bias = (z == 0) ? bQ : (z == 1) ? bK : bV;
    const float scale = (z == 0) ? 0.125f : 1.0f;

    const int tid  = threadIdx.x;
    const int w    = tid >> 5;
    const int lane = tid & 31;
    const int g    = lane >> 2;
    const int t4   = lane & 3;
    const int m0   = (w >> 1) * 32;
    const int n0   = (w & 1) * 64;
    const int bm   = blockIdx.y * 128;
    const int bn   = blockIdx.x * 128;

    const int arow  = tid >> 1;
    const int ahalf = (tid & 1) * 8;
    const int aswz  = (ahalf & 8) << 1;
    const int brow  = tid >> 4;
    const int bcolg = (tid & 15) * 8;

    float acc[2][8][4];
#pragma unroll
    for (int mi = 0; mi < 2; mi++)
#pragma unroll
        for (int ni = 0; ni < 8; ni++)
#pragma unroll
            for (int r = 0; r < 4; r++) acc[mi][ni][r] = 0.f;

    for (int k0 = 0; k0 < IN_DIM; k0 += 16) {
        float4 av0 = *(const float4*)&A[(size_t)(bm + arow) * IN_DIM + k0 + ahalf];
        float4 av1 = *(const float4*)&A[(size_t)(bm + arow) * IN_DIM + k0 + ahalf + 4];
        float4 bv0 = *(const float4*)&W[(size_t)(k0 + brow) * HD + bn + bcolg];
        float4 bv1 = *(const float4*)&W[(size_t)(k0 + brow) * HD + bn + bcolg + 4];
        __syncthreads();
        {
            const int mi_ = arow ^ aswz;
            As[(ahalf + 0) * 136 + mi_] = av0.x;
            As[(ahalf + 1) * 136 + mi_] = av0.y;
            As[(ahalf + 2) * 136 + mi_] = av0.z;
            As[(ahalf + 3) * 136 + mi_] = av0.w;
            As[(ahalf + 4) * 136 + mi_] = av1.x;
            As[(ahalf + 5) * 136 + mi_] = av1.y;
            As[(ahalf + 6) * 136 + mi_] = av1.z;
            As[(ahalf + 7) * 136 + mi_] = av1.w;
            *(float4*)&Bs[brow * 136 + bcolg]     = bv0;
            *(float4*)&Bs[brow * 136 + bcolg + 4] = bv1;
        }
        __syncthreads();

#pragma unroll
        for (int s = 0; s < 2; s++) {
            const int swz = s << 4;
            unsigned ah[2][4], al[2][4];
#pragma unroll
            for (int mi = 0; mi < 2; mi++) {
                const int mrow = m0 + mi * 16 + g;
                tf32_split(As[(s * 8 + t4) * 136 + (mrow ^ swz)],        ah[mi][0], al[mi][0]);
                tf32_split(As[(s * 8 + t4) * 136 + ((mrow + 8) ^ swz)],  ah[mi][1], al[mi][1]);
                tf32_split(As[(s * 8 + t4 + 4) * 136 + (mrow ^ swz)],       ah[mi][2], al[mi][2]);
                tf32_split(As[(s * 8 + t4 + 4) * 136 + ((mrow + 8) ^ swz)], ah[mi][3], al[mi][3]);
            }
#pragma unroll
            for (int ni = 0; ni < 8; ni++) {
                unsigned bh0, bl0, bh1, bl1;
                tf32_split(Bs[(s * 8 + t4) * 136 + n0 + ni * 8 + g],     bh0, bl0);
                tf32_split(Bs[(s * 8 + t4 + 4) * 136 + n0 + ni * 8 + g], bh1, bl1);
#pragma unroll
                for (int mi = 0; mi < 2; mi++) {
                    mma_tf32(acc[mi][ni], ah[mi], bh0, bh1);  // hi*hi
                    mma_tf32(acc[mi][ni], ah[mi], bl0, bl1);  // hi*lo
                    mma_tf32(acc[mi][ni], al[mi], bh0, bh1);  // lo*hi
                }
            }
        }
    }

#pragma unroll
    for (int mi = 0; mi < 2; mi++) {
        const int r0 = bm + m0 + mi * 16 + g;
#pragma unroll
        for (int ni = 0; ni < 8; ni++) {
            const int col = bn + n0 + ni * 8 + 2 * t4;
            const float b0 = bias[col], b1 = bias[col + 1];
            float v00 = (acc[mi][ni][0] + b0) * scale;
            float v01 = (acc[mi][ni][1] + b1) * scale;
            float v10 = (acc[mi][ni][2] + b0) * scale;
            float v11 = (acc[mi][ni][3] + b1) * scale;
            if (z < 2) {
                __half* Ch = (z == 0) ? qp : kp;
                *(__half2*)&Ch[(size_t)r0 * HD + col]       = __floats2half2_rn(v00, v01);
                *(__half2*)&Ch[(size_t)(r0 + 8) * HD + col] = __floats2half2_rn(v10, v11);
            } else {
                *(float2*)&vp[(size_t)r0 * HD + col]       = make_float2(v00, v01);
                *(float2*)&vp[(size_t)(r0 + 8) * HD + col] = make_float2(v10, v11);
            }
        }
    }
}

// ---------------------------------------------------------------------------
// V transpose to fp16: g_vt[h][e][j] = (half)g_v[j][h*64+e].
// ---------------------------------------------------------------------------
__global__ __launch_bounds__(256) void v_trans() {
    __shared__ __half ts[64 * 72];
    const int tid = threadIdx.x;
    const int j0  = blockIdx.x * 64;
    const int h   = blockIdx.y;

    const int col4 = tid & 15;
    const int jr   = tid >> 4;
#pragma unroll
    for (int c = 0; c < 4; c++) {
        const int j = jr + 16 * c;
        float4 v4 = *(const float4*)&g_v[(size_t)(j0 + j) * HD + h * 64 + col4 * 4];
        __half2* d = (__half2*)&ts[j * 72 + col4 * 4];
        d[0] = __floats2half2_rn(v4.x, v4.y);
        d[1] = __floats2half2_rn(v4.z, v4.w);
    }
    __syncthreads();

    const int e0 = tid >> 3;
    const int jc = tid & 7;
#pragma unroll
    for (int c = 0; c < 2; c++) {
        const int e = e0 + 32 * c;
        __half tmp[8];
#pragma unroll
        for (int i = 0; i < 8; i++) tmp[i] = ts[(jc * 8 + i) * 72 + e];
        *(uint4*)&g_vt[((size_t)(h * 64 + e)) * N_NODES + j0 + jc * 8] = *(uint4*)tmp;
    }
}

// ---------------------------------------------------------------------------
// Attention, split-K(8), FULL fp16 tensor path:
//   S: fp16 m16n8k16, q A-frags in regs, k row-major fp16 smem (B-frag direct)
//   P: fp32 softmax -> packh2 (C-frag IS next A-frag, no shuffles)
//   PV: fp16 m16n8k16 vs V^T fp16 smem
// cp.async double-buffered k+v staging (18.4 KB per buffer).
// ---------------------------------------------------------------------------
#define KPH 72                                  // k pitch in halves: banks 4g+t4 cf
#define VPH 72                                  // vt pitch in halves
#define KB_BYTES (64 * KPH * 2)                 // 9216
#define BUF_BYTES (KB_BYTES + 64 * VPH * 2)     // 18432
#define BUF_HALVES (BUF_BYTES / 2)
#define ATT_SMEM  (2 * BUF_BYTES)               // 36864

__global__ __launch_bounds__(128, 3) void attn_mma(const float* __restrict__ adj) {
    extern __shared__ __half sh[];
    const unsigned sbase = (unsigned)__cvta_generic_to_shared(sh);

    const int tid  = threadIdx.x;
    const int w    = tid >> 5;
    const int lane = tid & 31;
    const int g    = lane >> 2;
    const int t4   = lane & 3;
    const int qb   = blockIdx.x;      // 0..31
    const int h    = blockIdx.y;      // 0..7
    const int zs   = blockIdx.z;      // 0..NSPLIT-1
    const int hoff = h * ATT_DIM;
    const int qrow0 = qb * 128 + w * 32;

    // staging maps (row = tid>>1, 32-half chunk = (tid&1)*32)
    const int srw = tid >> 1;
    const int sch = (tid & 1) * 32;
    const int kb0 = zs * KB_PER_SPLIT;
    const __half* vt = &g_vt[(size_t)hoff * N_NODES];

    // prologue: stage kb0 into buffer 0
    {
        const __half* kr = &g_kh[(size_t)((kb0 << 6) + srw) * HD + hoff + sch];
        unsigned kd = sbase + (srw * KPH + sch) * 2;
#pragma unroll
        for (int c = 0; c < 4; c++) cp16(kd + c * 16, kr + c * 8);
        const __half* vr = &vt[(size_t)srw * N_NODES + (kb0 << 6) + sch];
        unsigned vd = sbase + KB_BYTES + (srw * VPH + sch) * 2;
#pragma unroll
        for (int c = 0; c < 4; c++) cp16(vd + c * 16, vr + c * 8);
        asm volatile("cp.async.commit_group;" ::: "memory");
    }

    // q A-fragments (fp16 m16n8k16) resident in registers: 32 regs
    unsigned qa[2][4][4];
#pragma unroll
    for (int mi = 0; mi < 2; mi++) {
        const __half* r0 = &g_qh[(size_t)(qrow0 + mi * 16 + g) * HD + hoff];
        const __half* r1 = r0 + 8 * HD;
#pragma unroll
        for (int kcg = 0; kcg < 4; kcg++) {
            qa[mi][kcg][0] = *(const unsigned*)(r0 + kcg * 16 + 2 * t4);
            qa[mi][kcg][1] = *(const unsigned*)(r1 + kcg * 16 + 2 * t4);
            qa[mi][kcg][2] = *(const unsigned*)(r0 + kcg * 16 + 2 * t4 + 8);
            qa[mi][kcg][3] = *(const unsigned*)(r1 + kcg * 16 + 2 * t4 + 8);
        }
    }

    float acc[2][8][4];
#pragma unroll
    for (int mi = 0; mi < 2; mi++)
#pragma unroll
        for (int en = 0; en < 8; en++)
#pragma unroll
            for (int r = 0; r < 4; r++) acc[mi][en][r] = 0.f;
    float rsum[2][2] = {{0.f, 0.f}, {0.f, 0.f}};

    const size_t abase = (size_t)(qb * 128 + w * 32) * N_NODES;

    for (int i = 0; i < KB_PER_SPLIT; i++) {
        const int kb = kb0 + i;
        const int b  = i & 1;
        if (i + 1 < KB_PER_SPLIT) {
            const __half* kr = &g_kh[(size_t)(((kb + 1) << 6) + srw) * HD + hoff + sch];
            unsigned kd = sbase + (b ^ 1) * BUF_BYTES + (srw * KPH + sch) * 2;
#pragma unroll
            for (int c = 0; c < 4; c++) cp16(kd + c * 16, kr + c * 8);
            const __half* vr = &vt[(size_t)srw * N_NODES + ((kb + 1) << 6) + sch];
            unsigned vd = sbase + (b ^ 1) * BUF_BYTES + KB_BYTES + (srw * VPH + sch) * 2;
#pragma unroll
            for (int c = 0; c < 4; c++) cp16(vd + c * 16, vr + c * 8);
            asm volatile("cp.async.commit_group;" ::: "memory");
            asm volatile("cp.async.wait_group 1;" ::: "memory");
        } else {
            asm volatile("cp.async.wait_group 0;" ::: "memory");
        }
        __syncthreads();

        const __half* k_h = sh + b * BUF_HALVES;
        const __half* v_h = k_h + 64 * KPH;

#pragma unroll
        for (int n2 = 0; n2 < 4; n2++) {
            // adj for both 8-key tiles of this 16-key group
            const size_t cA = (size_t)(kb * 64 + n2 * 16 + 2 * t4);
            float2 aA0 = *(const float2*)&adj[abase + (size_t)g * N_NODES + cA];
            float2 aA1 = *(const float2*)&adj[abase + (size_t)(g + 8) * N_NODES + cA];
            float2 aA2 = *(const float2*)&adj[abase + (size_t)(16 + g) * N_NODES + cA];
            float2 aA3 = *(const float2*)&adj[abase + (size_t)(24 + g) * N_NODES + cA];
            float2 aB0 = *(const float2*)&adj[abase + (size_t)g * N_NODES + cA + 8];
            float2 aB1 = *(const float2*)&adj[abase + (size_t)(g + 8) * N_NODES + cA + 8];
            float2 aB2 = *(const float2*)&adj[abase + (size_t)(16 + g) * N_NODES + cA + 8];
            float2 aB3 = *(const float2*)&adj[abase + (size_t)(24 + g) * N_NODES + cA + 8];

            // ---- S: fp16 m16n8k16, two 8-key tiles x two m-tiles ----
            float sA0[4] = {0.f, 0.f, 0.f, 0.f};
            float sA1[4] = {0.f, 0.f, 0.f, 0.f};
            float sB0[4] = {0.f, 0.f, 0.f, 0.f};
            float sB1[4] = {0.f, 0.f, 0.f, 0.f};
            const __half* krA = k_h + (n2 * 16 + g) * KPH;
            const __half* krB = krA + 8 * KPH;
#pragma unroll
            for (int kcg = 0; kcg < 4; kcg++) {
                unsigned bA0 = *(const unsigned*)(krA + kcg * 16 + 2 * t4);
                unsigned bA1 = *(const unsigned*)(krA + kcg * 16 + 2 * t4 + 8);
                unsigned bB0 = *(const unsigned*)(krB + kcg * 16 + 2 * t4);
                unsigned bB1 = *(const unsigned*)(krB + kcg * 16 + 2 * t4 + 8);
                mma_f16(sA0, qa[0][kcg][0], qa[0][kcg][1], qa[0][kcg][2], qa[0][kcg][3], bA0, bA1);
                mma_f16(sA1, qa[1][kcg][0], qa[1][kcg][1], qa[1][kcg][2], qa[1][kcg][3], bA0, bA1);
                mma_f16(sB0, qa[0][kcg][0], qa[0][kcg][1], qa[0][kcg][2], qa[0][kcg][3], bB0, bB1);
                mma_f16(sB1, qa[1][kcg][0], qa[1][kcg][1], qa[1][kcg][2], qa[1][kcg][3], bB0, bB1);
            }

            // ---- softmax numerators (fp32) ----
            float pA00 = fast_p(sA0[0], aA0.x), pA01 = fast_p(sA0[1], aA0.y);
            float pA02 = fast_p(sA0[2], aA1.x), pA03 = fast_p(sA0[3], aA1.y);
            float pA10 = fast_p(sA1[0], aA2.x), pA11 = fast_p(sA1[1], aA2.y);
            float pA12 = fast_p(sA1[2], aA3.x), pA13 = fast_p(sA1[3], aA3.y);
            float pB00 = fast_p(sB0[0], aB0.x), pB01 = fast_p(sB0[1], aB0.y);
            float pB02 = fast_p(sB0[2], aB1.x), pB03 = fast_p(sB0[3], aB1.y);
            float pB10 = fast_p(sB1[0], aB2.x), pB11 = fast_p(sB1[1], aB2.y);
            float pB12 = fast_p(sB1[2], aB3.x), pB13 = fast_p(sB1[3], aB3.y);
            rsum[0][0] += pA00 + pA01 + pB00 + pB01;
            rsum[0][1] += pA02 + pA03 + pB02 + pB03;
            rsum[1][0] += pA10 + pA11 + pB10 + pB11;
            rsum[1][1] += pA12 + pA13 + pB12 + pB13;

            // ---- pack: C-frags ARE the fp16 A-frag for PV ----
            unsigned a0m0 = packh2(pA00, pA01), a1m0 = packh2(pA02, pA03);
            unsigned a2m0 = packh2(pB00, pB01), a3m0 = packh2(pB02, pB03);
            unsigned a0m1 = packh2(pA10, pA11), a1m1 = packh2(pA12, pA13);
            unsigned a2m1 = packh2(pB10, pB11), a3m1 = packh2(pB12, pB13);

            // ---- PV: fp16 m16n8k16, V^T[e][j] half2 loads ----
#pragma unroll
            for (int en = 0; en < 8; en++) {
                const __half* vrow = v_h + (en * 8 + g) * VPH + n2 * 16;
                unsigned b0 = *(const unsigned*)(vrow + 2 * t4);
                unsigned b1 = *(const unsigned*)(vrow + 2 * t4 + 8);
                mma_f16(acc[0][en], a0m0, a1m0, a2m0, a3m0, b0, b1);
                mma_f16(acc[1][en], a0m1, a1m1, a2m1, a3m1, b0, b1);
            }
        }
        __syncthreads();
    }

    // ---- partial row sums (reduce over t4) and unnormalized store ----
#pragma unroll
    for (int mi = 0; mi < 2; mi++)
#pragma unroll
        for (int r = 0; r < 2; r++) {
            float s = rsum[mi][r];
            s += __shfl_xor_sync(0xffffffffu, s, 1);
            s += __shfl_xor_sync(0xffffffffu, s, 2);
            rsum[mi][r] = s;
        }
    if (t4 == 0) {
        float* rp = &g_rsum[(size_t)(zs * 8 + h) * N_NODES];
        rp[qrow0 + g]      = rsum[0][0];
        rp[qrow0 + g + 8]  = rsum[0][1];
        rp[qrow0 + g + 16] = rsum[1][0];
        rp[qrow0 + g + 24] = rsum[1][1];
    }

    float* part = &g_part[(size_t)zs * N_NODES * HD];
#pragma unroll
    for (int mi = 0; mi < 2; mi++) {
        const int r0 = qrow0 + mi * 16 + g;
#pragma unroll
        for (int en = 0; en < 8; en++) {
            const int col = hoff + en * 8 + 2 * t4;
            *(float2*)&part[(size_t)r0 * HD + col] =
                make_float2(acc[mi][en][0], acc[mi][en][1]);
            *(float2*)&part[(size_t)(r0 + 8) * HD + col] =
                make_float2(acc[mi][en][2], acc[mi][en][3]);
        }
    }
}

// ---------------------------------------------------------------------------
// Combine split-K partials: g_att = (sum parts) / (sum rsums)
// ---------------------------------------------------------------------------
__global__ __launch_bounds__(256) void attn_reduce() {
    const int idx = blockIdx.x * 256 + threadIdx.x;   // float4 index
    const int row = idx >> 7;
    const int col = (idx & 127) << 2;
    const int h   = col >> 6;

    float rs = 0.f;
#pragma unroll
    for (int z = 0; z < NSPLIT; z++)
        rs += g_rsum[(size_t)(z * 8 + h) * N_NODES + row];

    float4 s = make_float4(0.f, 0.f, 0.f, 0.f);
#pragma unroll
    for (int z = 0; z < NSPLIT; z++) {
        float4 p = *(const float4*)&g_part[((size_t)z * N_NODES + row) * HD + col];
        s.x += p.x; s.y += p.y; s.z += p.z; s.w += p.w;
    }
    const float inv = __fdividef(1.f, rs);
    s.x *= inv; s.y *= inv; s.z *= inv; s.w *= inv;
    *(float4*)&g_att[(size_t)row * HD + col] = s;
}

// ---------------------------------------------------------------------------
// Output projection: out[4096,64] = g_att[4096,512] @ WO[512,64] + bO (fp32)
// BM=32 -> 128 CTAs.
// ---------------------------------------------------------------------------
__global__ __launch_bounds__(256) void out_gemm(const float* __restrict__ WO,
                                                const float* __restrict__ bO,
                                                float* __restrict__ out) {
    __shared__ float As[32 * 36];
    __shared__ float Bs[32 * 68];
    const int tid = threadIdx.x;
    const int tx = tid & 15, ty = tid >> 4;
    const int bm = blockIdx.x * 32;

    float acc[2][4];
#pragma unroll
    for (int a = 0; a < 2; a++)
#pragma unroll
        for (int b = 0; b < 4; b++) acc[a][b] = 0.f;

    const int ar  = tid >> 3;
    const int akg = (tid & 7) * 4;
    const int bk  = tid >> 3;
    const int bjg = (tid & 7) * 8;

    for (int k0 = 0; k0 < HD; k0 += 32) {
        __syncthreads();
        {
            float4 a4 = *(const float4*)&g_att[(size_t)(bm + ar) * HD + k0 + akg];
            As[(akg + 0) * 36 + ar] = a4.x;
            As[(akg + 1) * 36 + ar] = a4.y;
            As[(akg + 2) * 36 + ar] = a4.z;
            As[(akg + 3) * 36 + ar] = a4.w;
        }
#pragma unroll
        for (int c = 0; c < 2; c++)
            *(float4*)&Bs[bk * 68 + bjg + c * 4] =
                *(const float4*)&WO[(k0 + bk) * 64 + bjg + c * 4];
        __syncthreads();
#pragma unroll
        for (int kk = 0; kk < 32; kk++) {
            float a0 = As[kk * 36 + ty * 2];
            float a1 = As[kk * 36 + ty * 2 + 1];
            float4 b4 = *(float4*)&Bs[kk * 68 + tx * 4];
            float brr[4] = {b4.x, b4.y, b4.z, b4.w};
#pragma unroll
            for (int b = 0; b < 4; b++) {
                acc[0][b] += a0 * brr[b];
                acc[1][b] += a1 * brr[b];
            }
        }
    }

    float bl[4];
#pragma unroll
    for (int b = 0; b < 4; b++) bl[b] = bO[tx * 4 + b];
#pragma unroll
    for (int a = 0; a < 2; a++) {
        float4 o;
        o.x = acc[a][0] + bl[0];
        o.y = acc[a][1] + bl[1];
        o.z = acc[a][2] + bl[2];
        o.w = acc[a][3] + bl[3];
        *(float4*)&out[(size_t)(bm + ty * 2 + a) * 64 + tx * 4] = o;
    }
}

// ---------------------------------------------------------------------------
extern "C" void kernel_launch(void* const* d_in, const int* in_sizes, int n_in,
                              void* d_out, int out_size) {
    const float* Q   = (const float*)d_in[0];
    const float* K   = (const float*)d_in[1];
    const float* V   = (const float*)d_in[2];
    const float* adj = (const float*)d_in[3];
    const float* WQ  = (const float*)d_in[4];
    const float* bQ  = (const float*)d_in[5];
    const float* WK  = (const float*)d_in[6];
    const float* bK  = (const float*)d_in[7];
    const float* WV  = (const float*)d_in[8];
    const float* bV  = (const float*)d_in[9];
    const float* WO  = (const float*)d_in[10];
    const float* bO  = (const float*)d_in[11];
    float* out = (float*)d_out;

    __half *qp, *kp;
    float  *vp;
    cudaGetSymbolAddress((void**)&qp, g_qh);
    cudaGetSymbolAddress((void**)&kp, g_kh);
    cudaGetSymbolAddress((void**)&vp, g_v);

    proj_mma<<<dim3(HD / 128, N_NODES / 128, 3), 256>>>(
        Q, K, V, WQ, WK, WV, bQ, bK, bV, qp, kp, vp);

    v_trans<<<dim3(N_NODES / 64, 8), 256>>>();

    cudaFuncSetAttribute(attn_mma,
                         cudaFuncAttributeMaxDynamicSharedMemorySize, ATT_SMEM);
    attn_mma<<<dim3(32, 8, NSPLIT), 128, ATT_SMEM>>>(adj);
    attn_reduce<<<(N_NODES * HD / 4) / 256, 256>>>();

    out_gemm<<<N_NODES / 32, 256>>>(WO, bO, out);
}